// round 5
// baseline (speedup 1.0000x reference)
#include <cuda_runtime.h>
#include <cuda_bf16.h>
#include <math_constants.h>
#include <math.h>
#include <cstdint>

// ---------------------------------------------------------------------------
// Problem constants: B=4, L=1024, D=1024, H=16, HD=64
// ---------------------------------------------------------------------------
#define B_ 4
#define L_ 1024
#define D_ 1024
#define H_ 16
#define HD_ 64

// ---------------------------------------------------------------------------
// Device scratch (no cudaMalloc allowed)
// ---------------------------------------------------------------------------
__device__ __align__(16) float g_pos[2048 * 64];                 // 512 KB
__device__ __align__(16) float g_E[16 * 2048];                   // (rw-rr)·pos
__device__ __align__(16) __nv_bfloat16 g_xh[4096 * 1024];        // x hi
__device__ __align__(16) __nv_bfloat16 g_xl[4096 * 1024];        // x lo
__device__ __align__(16) __nv_bfloat16 g_wh[2048 * 1024];        // Wqv^T hi  [n][k]
__device__ __align__(16) __nv_bfloat16 g_wl[2048 * 1024];        // Wqv^T lo
__device__ __align__(16) float g_u[4096 * 1024];                 // q + r_r_bias
__device__ __align__(16) float g_v[4096 * 1024];                 // v
__device__ __align__(16) float g_S[(size_t)64 * 1024 * 1024];    // 256 MB logits
__device__ __align__(16) float g_pm[65536 * 8];                  // partial row max per k-tile
__device__ __align__(16) float g_ps[65536 * 8];                  // partial row sumexp
__device__ __align__(16) float g_m[65536];                       // row max
__device__ __align__(16) float g_inv[65536];                     // 1/Z

// ---------------------------------------------------------------------------
// K1: relative sinusoidal positional table. row p <-> position (p - L).
// ---------------------------------------------------------------------------
__global__ void k_pos() {
    int p = blockIdx.x;     // 0..2047
    int i = threadIdx.x;    // 0..63
    float val = 0.0f;
    if (p != 0) {
        const float scale = logf(10000.0f) / 31.0f;
        int hi = (i < 32) ? i : (i - 32);
        float freq = expf(-scale * (float)hi);
        float ang = (float)(p - 1024) * freq;
        val = (i < 32) ? sinf(ang) : cosf(ang);
    }
    g_pos[p * HD_ + i] = val;
}

// ---------------------------------------------------------------------------
// K2a/K2b: split-precision bf16 decomposition of x and Wqv (Wqv transposed).
// ---------------------------------------------------------------------------
__global__ __launch_bounds__(256) void k_decomp_x(const float* __restrict__ x) {
    int idx = blockIdx.x * 256 + threadIdx.x;        // 0..4194303
    float f = x[idx];
    __nv_bfloat16 h = __float2bfloat16(f);
    g_xh[idx] = h;
    g_xl[idx] = __float2bfloat16(f - __bfloat162float(h));
}
__global__ __launch_bounds__(256) void k_decomp_w(const float* __restrict__ W) {
    int idx = blockIdx.x * 256 + threadIdx.x;        // 0..2097151
    int k = idx >> 11, n = idx & 2047;               // W[k][n]
    float f = W[idx];
    __nv_bfloat16 h = __float2bfloat16(f);
    g_wh[n * 1024 + k] = h;
    g_wl[n * 1024 + k] = __float2bfloat16(f - __bfloat162float(h));
}

// ---------------------------------------------------------------------------
// K3: E[h][j] = sum_d (rw - rr)[h][d] * pos[j][d]
// ---------------------------------------------------------------------------
__global__ __launch_bounds__(256) void k_E(const float* __restrict__ rr,
                                           const float* __restrict__ rw) {
    int idx = blockIdx.x * 256 + threadIdx.x;        // h*2048 + j
    int h = idx >> 11, j = idx & 2047;
    float s = 0.0f;
#pragma unroll 8
    for (int d = 0; d < 64; d++)
        s += (rw[h * 64 + d] - rr[h * 64 + d]) * g_pos[j * 64 + d];
    g_E[idx] = s;
}

// ---------------------------------------------------------------------------
// K4: qv = x @ Wqv via mma.sync m16n8k16 bf16 split (hh + hl + lh).
// 128x128 block, 8 warps in 2x4 (each 64x32). Fragments loaded directly
// from global (k-pairs are contiguous for both A[m][k] and W^T[n][k]).
// Epilogue writes u = q + rr (cols < 1024) or v (cols >= 1024).
// ---------------------------------------------------------------------------
__device__ __forceinline__ void mma_bf16(float* c, const uint32_t* a, const uint32_t* b) {
    asm volatile(
        "mma.sync.aligned.m16n8k16.row.col.f32.bf16.bf16.f32 "
        "{%0,%1,%2,%3}, {%4,%5,%6,%7}, {%8,%9}, {%0,%1,%2,%3};"
        : "+f"(c[0]), "+f"(c[1]), "+f"(c[2]), "+f"(c[3])
        : "r"(a[0]), "r"(a[1]), "r"(a[2]), "r"(a[3]), "r"(b[0]), "r"(b[1]));
}

__global__ __launch_bounds__(256) void k_qv_mma(const float* __restrict__ rr) {
    int tid = threadIdx.x, wid = tid >> 5, lane = tid & 31;
    int brow = blockIdx.y * 128;     // M tile (x rows)
    int bcol = blockIdx.x * 128;     // N tile (qv cols)
    int wm = (wid >> 2) * 64;        // warp m-offset within block
    int wn = (wid & 3) * 32;         // warp n-offset within block
    int g = lane >> 2, t = lane & 3;

    float acc[4][4][4] = {};         // [mi][ni][reg]

    // row base pointers (uint32 view; 512 uint32 per 1024-half row)
    const uint32_t* xh = (const uint32_t*)g_xh;
    const uint32_t* xl = (const uint32_t*)g_xl;
    const uint32_t* wh = (const uint32_t*)g_wh;
    const uint32_t* wl = (const uint32_t*)g_wl;

#pragma unroll 2
    for (int k0 = 0; k0 < 1024; k0 += 16) {
        int kw = k0 >> 1;            // uint32 offset of k0
        uint32_t ah[4][4], al[4][4], bh[4][2], bl[4][2];
#pragma unroll
        for (int mi = 0; mi < 4; mi++) {
            size_t r0 = (size_t)(brow + wm + mi * 16 + g) * 512 + kw + t;
            ah[mi][0] = xh[r0];            al[mi][0] = xl[r0];
            ah[mi][2] = xh[r0 + 4];        al[mi][2] = xl[r0 + 4];
            ah[mi][1] = xh[r0 + 8 * 512];  al[mi][1] = xl[r0 + 8 * 512];
            ah[mi][3] = xh[r0 + 8 * 512 + 4]; al[mi][3] = xl[r0 + 8 * 512 + 4];
        }
#pragma unroll
        for (int ni = 0; ni < 4; ni++) {
            size_t r0 = (size_t)(bcol + wn + ni * 8 + g) * 512 + kw + t;
            bh[ni][0] = wh[r0]; bh[ni][1] = wh[r0 + 4];
            bl[ni][0] = wl[r0]; bl[ni][1] = wl[r0 + 4];
        }
#pragma unroll
        for (int mi = 0; mi < 4; mi++)
#pragma unroll
            for (int ni = 0; ni < 4; ni++) {
                mma_bf16(acc[mi][ni], ah[mi], bh[ni]);
                mma_bf16(acc[mi][ni], ah[mi], bl[ni]);
                mma_bf16(acc[mi][ni], al[mi], bh[ni]);
            }
    }

    // epilogue: c0=(g,2t) c1=(g,2t+1) c2=(g+8,2t) c3=(g+8,2t+1)
    bool is_q = (bcol < 1024);
#pragma unroll
    for (int mi = 0; mi < 4; mi++) {
#pragma unroll
        for (int ni = 0; ni < 4; ni++) {
            int row0 = brow + wm + mi * 16 + g;
            int cn = bcol + wn + ni * 8 + 2 * t;
            float2 v0 = make_float2(acc[mi][ni][0], acc[mi][ni][1]);
            float2 v1 = make_float2(acc[mi][ni][2], acc[mi][ni][3]);
            if (is_q) {
                float2 rb = *(const float2*)(rr + cn);
                v0.x += rb.x; v0.y += rb.y;
                v1.x += rb.x; v1.y += rb.y;
                *(float2*)&g_u[(size_t)row0 * 1024 + cn] = v0;
                *(float2*)&g_u[(size_t)(row0 + 8) * 1024 + cn] = v1;
            } else {
                *(float2*)&g_v[(size_t)row0 * 1024 + cn - 1024] = v0;
                *(float2*)&g_v[(size_t)(row0 + 8) * 1024 + cn - 1024] = v1;
            }
        }
    }
}

// ---------------------------------------------------------------------------
// K5: fused S-writer. S[q,k] = u·x_k + u·pos[k-q+L] + E[h,k-q+L], masked,
// plus per-(row, k-tile) partial softmax stats. 128x128 tile, 8x8 micro.
// ---------------------------------------------------------------------------
__global__ __launch_bounds__(256) void k_swriter(const float* __restrict__ x,
                                                 const int* __restrict__ mask) {
    __shared__ float As[16][128];   // u tile (kk-major)
    __shared__ float Bs[16][128];   // x-key tile
    __shared__ float Ps[16][256];   // pos band (255 rows used)
    __shared__ float Es[256];       // E band
    __shared__ int   msk[128];
    int bh = blockIdx.z, b = bh >> 4, h = bh & 15;
    int brow = blockIdx.y * 128;    // q tile
    int bcol = blockIdx.x * 128;    // k tile
    int jbase = bcol - brow + 897;  // in [1,1793]
    int tid = threadIdx.x, tx = tid & 15, ty = tid >> 4;

    if (tid < 255) Es[tid] = g_E[h * 2048 + jbase + tid];
    if (tid < 128) msk[tid] = mask[b * 1024 + bcol + tid];

    const float* ub = g_u + (size_t)(b * 1024 + brow) * 1024 + h * 64;
    const float* xb = x   + (size_t)(b * 1024 + bcol) * 1024 + h * 64;

    float acc[8][8] = {};
    for (int k0 = 0; k0 < 64; k0 += 16) {
#pragma unroll
        for (int i = 0; i < 2; i++) {
            int idx = tid * 2 + i;              // 0..511
            int r = idx >> 2;                   // 0..127
            int c4 = (idx & 3) * 4;
            float4 va = *(const float4*)(ub + (size_t)r * 1024 + k0 + c4);
            As[c4 + 0][r] = va.x; As[c4 + 1][r] = va.y;
            As[c4 + 2][r] = va.z; As[c4 + 3][r] = va.w;
            float4 vk = *(const float4*)(xb + (size_t)r * 1024 + k0 + c4);
            Bs[c4 + 0][r] = vk.x; Bs[c4 + 1][r] = vk.y;
            Bs[c4 + 2][r] = vk.z; Bs[c4 + 3][r] = vk.w;
        }
        if (tid < 255) {
            const float* pp = g_pos + (size_t)(jbase + tid) * 64 + k0;
#pragma unroll
            for (int ii = 0; ii < 4; ii++) {
                float4 vp = *(const float4*)(pp + ii * 4);
                Ps[ii * 4 + 0][tid] = vp.x; Ps[ii * 4 + 1][tid] = vp.y;
                Ps[ii * 4 + 2][tid] = vp.z; Ps[ii * 4 + 3][tid] = vp.w;
            }
        }
        __syncthreads();
        int pb = tx * 8 - ty * 8 + 120;
#pragma unroll
        for (int kk = 0; kk < 16; kk++) {
            float ar[8], br[8], pr[15];
#pragma unroll
            for (int i = 0; i < 8; i++) ar[i] = As[kk][ty * 8 + i];
#pragma unroll
            for (int j = 0; j < 8; j++) br[j] = Bs[kk][tx * 8 + j];
#pragma unroll
            for (int t = 0; t < 15; t++) pr[t] = Ps[kk][pb + t];
#pragma unroll
            for (int i = 0; i < 8; i++) {
                float a = ar[i];
#pragma unroll
                for (int j = 0; j < 8; j++) {
                    acc[i][j] = fmaf(a, br[j], acc[i][j]);
                    acc[i][j] = fmaf(a, pr[j - i + 7], acc[i][j]);
                }
            }
        }
        __syncthreads();
    }

    // epilogue: add E band, mask, write S, emit partial row stats
    float* Sb = g_S + (size_t)bh * 1024 * 1024;
#pragma unroll
    for (int i = 0; i < 8; i++) {
        int lq = ty * 8 + i;
        float vals[8];
        float vmax = -CUDART_INF_F;
#pragma unroll
        for (int j = 0; j < 8; j++) {
            int lk = tx * 8 + j;
            float v = acc[i][j] + Es[lk - lq + 127];
            if (msk[lk] == 0) v = -CUDART_INF_F;
            vals[j] = v;
            vmax = fmaxf(vmax, v);
        }
#pragma unroll
        for (int o = 8; o; o >>= 1) vmax = fmaxf(vmax, __shfl_xor_sync(0xffffffffu, vmax, o));
        float ssum = 0.0f;
#pragma unroll
        for (int j = 0; j < 8; j++) {
            float e = (vals[j] == -CUDART_INF_F) ? 0.0f : __expf(vals[j] - vmax);
            ssum += e;
        }
#pragma unroll
        for (int o = 8; o; o >>= 1) ssum += __shfl_xor_sync(0xffffffffu, ssum, o);

        float* row = Sb + (size_t)(brow + lq) * 1024 + bcol + tx * 8;
        *(float4*)(row)     = make_float4(vals[0], vals[1], vals[2], vals[3]);
        *(float4*)(row + 4) = make_float4(vals[4], vals[5], vals[6], vals[7]);
        if (tx == 0) {
            size_t sidx = ((size_t)bh * 1024 + brow + lq) * 8 + blockIdx.x;
            g_pm[sidx] = vmax;
            g_ps[sidx] = ssum;
        }
    }
}

// ---------------------------------------------------------------------------
// K6: combine partial softmax stats -> row max + 1/Z
// ---------------------------------------------------------------------------
__global__ __launch_bounds__(256) void k_combine() {
    int r = blockIdx.x * 256 + threadIdx.x;  // 0..65535
    float m = -CUDART_INF_F;
#pragma unroll
    for (int t = 0; t < 8; t++) m = fmaxf(m, g_pm[r * 8 + t]);
    float z = 0.0f;
#pragma unroll
    for (int t = 0; t < 8; t++) {
        float s = g_ps[r * 8 + t];
        if (s > 0.0f) z += s * __expf(g_pm[r * 8 + t] - m);
    }
    g_m[r] = m;
    g_inv[r] = 1.0f / z;
}

// ---------------------------------------------------------------------------
// K7: PV with fused softmax. out = softmax(S) @ v per (b,h).
// 128x64 tile, K loop 1024 step 16, 8x4 micro.  Grid: (8 q-tiles, 64 bh).
// ---------------------------------------------------------------------------
__global__ __launch_bounds__(256) void k_pv(float* __restrict__ out) {
    const int BK = 16;
    __shared__ float As[BK][128];
    __shared__ float Bs[BK][64];
    __shared__ float ms[128], invs[128];
    int bh = blockIdx.y;
    int b = bh >> 4, h = bh & 15;
    int brow = blockIdx.x * 128;
    int tid = threadIdx.x;
    int tx = tid & 15, ty = tid >> 4;
    const float* Sb = g_S + (size_t)bh * 1024 * 1024;
    const float* vbase = g_v + (size_t)(b * 1024) * 1024 + h * 64;

    if (tid < 128) {
        int rg = bh * 1024 + brow + tid;
        ms[tid] = g_m[rg];
        invs[tid] = g_inv[rg];
    }
    __syncthreads();

    float acc[8][4] = {};
    for (int k0 = 0; k0 < 1024; k0 += BK) {
#pragma unroll
        for (int i = 0; i < 2; i++) {
            int idx = tid * 2 + i;             // 0..511
            int r = idx >> 2;                  // 0..127 attn row
            int c4 = (idx & 3) * 4;            // 0..12
            float4 va = *(const float4*)(Sb + (size_t)(brow + r) * 1024 + k0 + c4);
            float mr = ms[r], ir = invs[r];
            As[c4 + 0][r] = __expf(va.x - mr) * ir;
            As[c4 + 1][r] = __expf(va.y - mr) * ir;
            As[c4 + 2][r] = __expf(va.z - mr) * ir;
            As[c4 + 3][r] = __expf(va.w - mr) * ir;
        }
        {
            int rb = tid >> 4;                 // 0..15 v k-row
            int cb4 = (tid & 15) * 4;          // 0..60
            *(float4*)&Bs[rb][cb4] = *(const float4*)(vbase + (size_t)(k0 + rb) * 1024 + cb4);
        }
        __syncthreads();
#pragma unroll
        for (int kk = 0; kk < BK; kk++) {
            float ar[8], br[4];
#pragma unroll
            for (int i = 0; i < 8; i++) ar[i] = As[kk][ty * 8 + i];
#pragma unroll
            for (int j = 0; j < 4; j++) br[j] = Bs[kk][tx * 4 + j];
#pragma unroll
            for (int i = 0; i < 8; i++)
#pragma unroll
                for (int j = 0; j < 4; j++)
                    acc[i][j] = fmaf(ar[i], br[j], acc[i][j]);
        }
        __syncthreads();
    }
#pragma unroll
    for (int i = 0; i < 8; i++) {
        float4 v = make_float4(acc[i][0], acc[i][1], acc[i][2], acc[i][3]);
        *(float4*)(out + (size_t)(b * 1024 + brow + ty * 8 + i) * 1024 + h * 64 + tx * 4) = v;
    }
}

// ---------------------------------------------------------------------------
extern "C" void kernel_launch(void* const* d_in, const int* in_sizes, int n_in,
                              void* d_out, int out_size) {
    (void)in_sizes; (void)n_in; (void)out_size;
    const float* x    = (const float*)d_in[0];   // [4,1024,1024]
    const float* Wqv  = (const float*)d_in[1];   // [1024,2048]
    const float* rr   = (const float*)d_in[2];   // [16,64]
    const float* rw   = (const float*)d_in[3];   // [16,64]
    const int*   mask = (const int*)d_in[4];     // [4,1024]
    float* out = (float*)d_out;                  // [4,1024,1024]

    k_pos<<<2048, 64>>>();
    k_decomp_x<<<16384, 256>>>(x);
    k_decomp_w<<<8192, 256>>>(Wqv);
    k_E<<<128, 256>>>(rr, rw);
    k_qv_mma<<<dim3(16, 32), 256>>>(rr);
    k_swriter<<<dim3(8, 8, 64), 256>>>(x, mask);
    k_combine<<<256, 256>>>();
    k_pv<<<dim3(8, 64), 256>>>(out);     // FIX: 8 q-tiles of 128 rows (was 16 -> OOB)
}

// round 6
// speedup vs baseline: 1.0291x; 1.0291x over previous
#include <cuda_runtime.h>
#include <cuda_bf16.h>
#include <math_constants.h>
#include <math.h>
#include <cstdint>

// B=4, L=1024, D=1024, H=16, HD=64.
// S[q,k] = (q+rr)·x_k + (q+rw)·pos[k-q+L]  ==  Â[q]·K̂[k]  with K=128 (angle addition).

// ---------------------------------------------------------------------------
// Device scratch
// ---------------------------------------------------------------------------
__device__ __align__(16) __nv_bfloat16 g_xh[4096 * 1024];
__device__ __align__(16) __nv_bfloat16 g_xl[4096 * 1024];
__device__ __align__(16) __nv_bfloat16 g_wh[2048 * 1024];      // Wqv^T hi [n][k]
__device__ __align__(16) __nv_bfloat16 g_wl[2048 * 1024];
__device__ __align__(16) float g_u[4096 * 1024];               // q + rr
__device__ __align__(16) float g_v[4096 * 1024];               // v fp32
__device__ __align__(16) __nv_bfloat16 g_vth[64 * 64 * 1024];  // V^T hi [bh*64+d][tok]
__device__ __align__(16) __nv_bfloat16 g_vtl[64 * 64 * 1024];  // V^T lo
__device__ __align__(16) float g_trig[1024 * 64];              // [p][i]=sin(p f_i), [p][32+i]=cos
__device__ __align__(16) __nv_bfloat16 g_Ah[(size_t)64 * 1024 * 128];
__device__ __align__(16) __nv_bfloat16 g_Al[(size_t)64 * 1024 * 128];
__device__ __align__(16) __nv_bfloat16 g_Kh[(size_t)64 * 1024 * 128];
__device__ __align__(16) __nv_bfloat16 g_Kl[(size_t)64 * 1024 * 128];
__device__ __align__(16) float g_S[(size_t)64 * 1024 * 1024];  // 256 MB
__device__ __align__(16) float g_pm[(size_t)65536 * 32];       // partial max per 32-k slice
__device__ __align__(16) float g_ps[(size_t)65536 * 32];
__device__ __align__(16) float g_m[65536];
__device__ __align__(16) float g_inv[65536];

// ---------------------------------------------------------------------------
__device__ __forceinline__ void mma_bf16(float* c, const uint32_t* a, const uint32_t* b) {
    asm volatile(
        "mma.sync.aligned.m16n8k16.row.col.f32.bf16.bf16.f32 "
        "{%0,%1,%2,%3}, {%4,%5,%6,%7}, {%8,%9}, {%0,%1,%2,%3};"
        : "+f"(c[0]), "+f"(c[1]), "+f"(c[2]), "+f"(c[3])
        : "r"(a[0]), "r"(a[1]), "r"(a[2]), "r"(a[3]), "r"(b[0]), "r"(b[1]));
}
__device__ __forceinline__ uint32_t pack2(float e0, float e1) {
    __nv_bfloat162 h;
    h.x = __float2bfloat16(e0);
    h.y = __float2bfloat16(e1);
    return *(uint32_t*)&h;
}

// ---------------------------------------------------------------------------
// K0: trig table (fp64 source). g_trig[p][i]=sin(p f_i), [p][32+i]=cos(p f_i)
// ---------------------------------------------------------------------------
__global__ void k_trig() {
    int p = blockIdx.x, i = threadIdx.x;   // 1024 x 32
    double f = exp(-(double)i * (log(10000.0) / 31.0));
    double ang = (double)p * f;
    g_trig[p * 64 + i] = (float)sin(ang);
    g_trig[p * 64 + 32 + i] = (float)cos(ang);
}

// ---------------------------------------------------------------------------
// K1: bf16 hi/lo decomposition of x and Wqv^T
// ---------------------------------------------------------------------------
__global__ __launch_bounds__(256) void k_decomp_x(const float* __restrict__ x) {
    int idx = blockIdx.x * 256 + threadIdx.x;
    float f = x[idx];
    __nv_bfloat16 h = __float2bfloat16(f);
    g_xh[idx] = h;
    g_xl[idx] = __float2bfloat16(f - __bfloat162float(h));
}
__global__ __launch_bounds__(256) void k_decomp_w(const float* __restrict__ W) {
    int idx = blockIdx.x * 256 + threadIdx.x;
    int k = idx >> 11, n = idx & 2047;
    float f = W[idx];
    __nv_bfloat16 h = __float2bfloat16(f);
    g_wh[n * 1024 + k] = h;
    g_wl[n * 1024 + k] = __float2bfloat16(f - __bfloat162float(h));
}

// ---------------------------------------------------------------------------
// K2: qv = x @ Wqv via mma.sync bf16 3-split. (validated in R4)
// ---------------------------------------------------------------------------
__global__ __launch_bounds__(256) void k_qv_mma(const float* __restrict__ rr) {
    int tid = threadIdx.x, wid = tid >> 5, lane = tid & 31;
    int brow = blockIdx.y * 128, bcol = blockIdx.x * 128;
    int wm = (wid >> 2) * 64, wn = (wid & 3) * 32;
    int g = lane >> 2, t = lane & 3;
    float acc[4][4][4] = {};
    const uint32_t* xh = (const uint32_t*)g_xh;
    const uint32_t* xl = (const uint32_t*)g_xl;
    const uint32_t* wh = (const uint32_t*)g_wh;
    const uint32_t* wl = (const uint32_t*)g_wl;

#pragma unroll 2
    for (int k0 = 0; k0 < 1024; k0 += 16) {
        int kw = k0 >> 1;
        uint32_t ah[4][4], al[4][4], bh[4][2], bl[4][2];
#pragma unroll
        for (int mi = 0; mi < 4; mi++) {
            size_t r0 = (size_t)(brow + wm + mi * 16 + g) * 512 + kw + t;
            ah[mi][0] = xh[r0];               al[mi][0] = xl[r0];
            ah[mi][2] = xh[r0 + 4];           al[mi][2] = xl[r0 + 4];
            ah[mi][1] = xh[r0 + 8 * 512];     al[mi][1] = xl[r0 + 8 * 512];
            ah[mi][3] = xh[r0 + 8 * 512 + 4]; al[mi][3] = xl[r0 + 8 * 512 + 4];
        }
#pragma unroll
        for (int ni = 0; ni < 4; ni++) {
            size_t r0 = (size_t)(bcol + wn + ni * 8 + g) * 512 + kw + t;
            bh[ni][0] = wh[r0]; bh[ni][1] = wh[r0 + 4];
            bl[ni][0] = wl[r0]; bl[ni][1] = wl[r0 + 4];
        }
#pragma unroll
        for (int mi = 0; mi < 4; mi++)
#pragma unroll
            for (int ni = 0; ni < 4; ni++) {
                mma_bf16(acc[mi][ni], ah[mi], bh[ni]);
                mma_bf16(acc[mi][ni], ah[mi], bl[ni]);
                mma_bf16(acc[mi][ni], al[mi], bh[ni]);
            }
    }
    bool is_q = (bcol < 1024);
#pragma unroll
    for (int mi = 0; mi < 4; mi++)
#pragma unroll
        for (int ni = 0; ni < 4; ni++) {
            int row0 = brow + wm + mi * 16 + g;
            int cn = bcol + wn + ni * 8 + 2 * t;
            float2 v0 = make_float2(acc[mi][ni][0], acc[mi][ni][1]);
            float2 v1 = make_float2(acc[mi][ni][2], acc[mi][ni][3]);
            if (is_q) {
                float2 rb = *(const float2*)(rr + cn);
                v0.x += rb.x; v0.y += rb.y;
                v1.x += rb.x; v1.y += rb.y;
                *(float2*)&g_u[(size_t)row0 * 1024 + cn] = v0;
                *(float2*)&g_u[(size_t)(row0 + 8) * 1024 + cn] = v1;
            } else {
                *(float2*)&g_v[(size_t)row0 * 1024 + cn - 1024] = v0;
                *(float2*)&g_v[(size_t)(row0 + 8) * 1024 + cn - 1024] = v1;
            }
        }
}

// ---------------------------------------------------------------------------
// K3: V^T bf16 hi/lo.  g_vt[(bh*64+d)*1024 + tok] = v[(b*1024+tok)*1024+h*64+d]
// ---------------------------------------------------------------------------
__global__ __launch_bounds__(256) void k_vt() {
    int idx = blockIdx.x * 256 + threadIdx.x;   // 4194304
    int tok = idx & 1023, d = (idx >> 10) & 63, bh = idx >> 16;
    int b = bh >> 4, h = bh & 15;
    float f = g_v[(size_t)(b * 1024 + tok) * 1024 + h * 64 + d];
    __nv_bfloat16 hi = __float2bfloat16(f);
    g_vth[idx] = hi;
    g_vtl[idx] = __float2bfloat16(f - __bfloat162float(hi));
}

// ---------------------------------------------------------------------------
// K4a: Â rows.  [0:64)=u ; [64+i)=w_i c_q + w_{32+i} s_q ; [96+i)=w_{32+i} c_q - w_i s_q
//      u = q+rr (from K2); w = u - rr + rw.
// ---------------------------------------------------------------------------
__global__ __launch_bounds__(256) void k_build_A(const float* __restrict__ rr,
                                                 const float* __restrict__ rw) {
    int idx = blockIdx.x * 256 + threadIdx.x;   // 65536 rows
    int bh = idx >> 10, q = idx & 1023;
    int b = bh >> 4, h = bh & 15;
    const float* up = g_u + (size_t)(b * 1024 + q) * 1024 + h * 64;
    __nv_bfloat16* ah = g_Ah + (size_t)idx * 128;
    __nv_bfloat16* al = g_Al + (size_t)idx * 128;
    const float* tg = g_trig + q * 64;
#pragma unroll 8
    for (int i = 0; i < 32; i++) {
        float u0 = up[i], u1 = up[32 + i];
        __nv_bfloat16 h0 = __float2bfloat16(u0);
        ah[i] = h0; al[i] = __float2bfloat16(u0 - __bfloat162float(h0));
        __nv_bfloat16 h1 = __float2bfloat16(u1);
        ah[32 + i] = h1; al[32 + i] = __float2bfloat16(u1 - __bfloat162float(h1));
        float w0 = u0 - rr[h * 64 + i] + rw[h * 64 + i];
        float w1 = u1 - rr[h * 64 + 32 + i] + rw[h * 64 + 32 + i];
        float sq = tg[i], cq = tg[32 + i];
        float a1 = w0 * cq + w1 * sq;
        float a2 = w1 * cq - w0 * sq;
        __nv_bfloat16 hh1 = __float2bfloat16(a1);
        ah[64 + i] = hh1; al[64 + i] = __float2bfloat16(a1 - __bfloat162float(hh1));
        __nv_bfloat16 hh2 = __float2bfloat16(a2);
        ah[96 + i] = hh2; al[96 + i] = __float2bfloat16(a2 - __bfloat162float(hh2));
    }
}

// K4b: K̂ rows.  [0:64)=x slice ; [64+i)=sin(k f_i) ; [96+i)=cos(k f_i)
__global__ __launch_bounds__(256) void k_build_K(const float* __restrict__ x) {
    int idx = blockIdx.x * 256 + threadIdx.x;
    int bh = idx >> 10, k = idx & 1023;
    int b = bh >> 4, h = bh & 15;
    const float* xp = x + (size_t)(b * 1024 + k) * 1024 + h * 64;
    __nv_bfloat16* kh = g_Kh + (size_t)idx * 128;
    __nv_bfloat16* kl = g_Kl + (size_t)idx * 128;
    const float* tg = g_trig + k * 64;
#pragma unroll 8
    for (int i = 0; i < 32; i++) {
        float x0 = xp[i], x1 = xp[32 + i];
        __nv_bfloat16 h0 = __float2bfloat16(x0);
        kh[i] = h0; kl[i] = __float2bfloat16(x0 - __bfloat162float(h0));
        __nv_bfloat16 h1 = __float2bfloat16(x1);
        kh[32 + i] = h1; kl[32 + i] = __float2bfloat16(x1 - __bfloat162float(h1));
        float s = tg[i], c = tg[32 + i];
        __nv_bfloat16 h2 = __float2bfloat16(s);
        kh[64 + i] = h2; kl[64 + i] = __float2bfloat16(s - __bfloat162float(h2));
        __nv_bfloat16 h3 = __float2bfloat16(c);
        kh[96 + i] = h3; kl[96 + i] = __float2bfloat16(c - __bfloat162float(h3));
    }
}

// ---------------------------------------------------------------------------
// K5: S = Â·K̂^T (K=128) via mma.sync 3-split. 128x128 tile, 8 warps (2m x 4n).
// Epilogue: mask, store S, per-(row, 32k-slice) softmax partials.
// ---------------------------------------------------------------------------
__global__ __launch_bounds__(256) void k_sgemm(const int* __restrict__ mask) {
    __shared__ int msk[128];
    int bh = blockIdx.z, b = bh >> 4;
    int brow = blockIdx.y * 128, bcol = blockIdx.x * 128;
    int tid = threadIdx.x, wid = tid >> 5, lane = tid & 31;
    int wm = (wid >> 2) * 64, wn = (wid & 3) * 32;
    int g = lane >> 2, t = lane & 3;
    if (tid < 128) msk[tid] = mask[b * 1024 + bcol + tid];
    __syncthreads();

    const uint32_t* Ah = (const uint32_t*)g_Ah;
    const uint32_t* Al = (const uint32_t*)g_Al;
    const uint32_t* Kh = (const uint32_t*)g_Kh;
    const uint32_t* Kl = (const uint32_t*)g_Kl;
    size_t abase = (size_t)(bh * 1024 + brow + wm) * 64;
    size_t kbase = (size_t)(bh * 1024 + bcol + wn) * 64;

    float acc[4][4][4] = {};
#pragma unroll
    for (int k0 = 0; k0 < 128; k0 += 16) {
        int kw = k0 >> 1;
        uint32_t ah[4][4], al[4][4], bh2[4][2], bl2[4][2];
#pragma unroll
        for (int mi = 0; mi < 4; mi++) {
            size_t r0 = abase + (size_t)(mi * 16 + g) * 64 + kw + t;
            ah[mi][0] = Ah[r0];              al[mi][0] = Al[r0];
            ah[mi][2] = Ah[r0 + 4];          al[mi][2] = Al[r0 + 4];
            ah[mi][1] = Ah[r0 + 8 * 64];     al[mi][1] = Al[r0 + 8 * 64];
            ah[mi][3] = Ah[r0 + 8 * 64 + 4]; al[mi][3] = Al[r0 + 8 * 64 + 4];
        }
#pragma unroll
        for (int ni = 0; ni < 4; ni++) {
            size_t r0 = kbase + (size_t)(ni * 8 + g) * 64 + kw + t;
            bh2[ni][0] = Kh[r0]; bh2[ni][1] = Kh[r0 + 4];
            bl2[ni][0] = Kl[r0]; bl2[ni][1] = Kl[r0 + 4];
        }
#pragma unroll
        for (int mi = 0; mi < 4; mi++)
#pragma unroll
            for (int ni = 0; ni < 4; ni++) {
                mma_bf16(acc[mi][ni], ah[mi], bh2[ni]);
                mma_bf16(acc[mi][ni], ah[mi], bl2[ni]);
                mma_bf16(acc[mi][ni], al[mi], bh2[ni]);
            }
    }

    // epilogue: two rows per (mi): rg = wm+mi*16+g and +8
    float* Sb = g_S + (size_t)bh * 1024 * 1024;
#pragma unroll
    for (int half = 0; half < 2; half++) {         // 0: rows g, 1: rows g+8
#pragma unroll
        for (int mi = 0; mi < 4; mi++) {
            int rloc = wm + mi * 16 + g + half * 8;
            float vmax = -CUDART_INF_F, vsum = 0.0f;
            float2 vs[4];
#pragma unroll
            for (int ni = 0; ni < 4; ni++) {
                int lk = wn + ni * 8 + 2 * t;
                float v0 = acc[mi][ni][half * 2 + 0];
                float v1 = acc[mi][ni][half * 2 + 1];
                if (msk[lk] == 0)     v0 = -CUDART_INF_F;
                if (msk[lk + 1] == 0) v1 = -CUDART_INF_F;
                vs[ni] = make_float2(v0, v1);
                vmax = fmaxf(vmax, fmaxf(v0, v1));
            }
            // quad reduce max over t (lanes g*4+t)
            vmax = fmaxf(vmax, __shfl_xor_sync(0xffffffffu, vmax, 1));
            vmax = fmaxf(vmax, __shfl_xor_sync(0xffffffffu, vmax, 2));
#pragma unroll
            for (int ni = 0; ni < 4; ni++) {
                float v0 = vs[ni].x, v1 = vs[ni].y;
                vsum += (v0 == -CUDART_INF_F) ? 0.0f : __expf(v0 - vmax);
                vsum += (v1 == -CUDART_INF_F) ? 0.0f : __expf(v1 - vmax);
                *(float2*)&Sb[(size_t)(brow + rloc) * 1024 + bcol + wn + ni * 8 + 2 * t] = vs[ni];
            }
            vsum += __shfl_xor_sync(0xffffffffu, vsum, 1);
            vsum += __shfl_xor_sync(0xffffffffu, vsum, 2);
            if (t == 0) {
                size_t sidx = ((size_t)bh * 1024 + brow + rloc) * 32 + blockIdx.x * 4 + (wid & 3);
                g_pm[sidx] = vmax;
                g_ps[sidx] = vsum;
            }
        }
    }
}

// ---------------------------------------------------------------------------
// K6: combine 32 partials per row -> row max + 1/Z
// ---------------------------------------------------------------------------
__global__ __launch_bounds__(256) void k_combine() {
    int r = blockIdx.x * 256 + threadIdx.x;
    float m = -CUDART_INF_F;
#pragma unroll 8
    for (int t = 0; t < 32; t++) m = fmaxf(m, g_pm[(size_t)r * 32 + t]);
    float z = 0.0f;
#pragma unroll 8
    for (int t = 0; t < 32; t++) {
        float s = g_ps[(size_t)r * 32 + t];
        if (s > 0.0f) z += s * __expf(g_pm[(size_t)r * 32 + t] - m);
    }
    g_m[r] = m;
    g_inv[r] = 1.0f / z;
}

// ---------------------------------------------------------------------------
// K7: out = softmax(S) @ V via mma.sync. Block 256q x 64d, 8 warps (4m x 2n).
// P computed on the fly (exp·inv, hi/lo split); V^T bf16 hi/lo pre-built.
// ---------------------------------------------------------------------------
__global__ __launch_bounds__(256) void k_pv_mma(float* __restrict__ out) {
    int bh = blockIdx.y, b = bh >> 4, h = bh & 15;
    int brow = blockIdx.x * 256;
    int tid = threadIdx.x, wid = tid >> 5, lane = tid & 31;
    int wm = (wid >> 1) * 64, wn = (wid & 1) * 32;
    int g = lane >> 2, t = lane & 3;

    const float* Sb = g_S + (size_t)bh * 1024 * 1024;
    const uint32_t* Vh = (const uint32_t*)g_vth;
    const uint32_t* Vl = (const uint32_t*)g_vtl;

    float mrow[4][2], irow[4][2];
#pragma unroll
    for (int mi = 0; mi < 4; mi++) {
        int r0 = bh * 1024 + brow + wm + mi * 16 + g;
        mrow[mi][0] = g_m[r0];     irow[mi][0] = g_inv[r0];
        mrow[mi][1] = g_m[r0 + 8]; irow[mi][1] = g_inv[r0 + 8];
    }

    float acc[4][4][4] = {};
    for (int k0 = 0; k0 < 1024; k0 += 16) {
        uint32_t ah[4][4], al[4][4], bh2[4][2], bl2[4][2];
#pragma unroll
        for (int mi = 0; mi < 4; mi++) {
            const float* r0 = Sb + (size_t)(brow + wm + mi * 16 + g) * 1024 + k0 + 2 * t;
            const float* r1 = r0 + 8 * 1024;
            float2 s0 = *(const float2*)(r0);
            float2 s2 = *(const float2*)(r0 + 8);
            float2 s1 = *(const float2*)(r1);
            float2 s3 = *(const float2*)(r1 + 8);
            float m0 = mrow[mi][0], i0 = irow[mi][0];
            float m1 = mrow[mi][1], i1 = irow[mi][1];
            float e00 = (s0.x == -CUDART_INF_F) ? 0.0f : __expf(s0.x - m0) * i0;
            float e01 = (s0.y == -CUDART_INF_F) ? 0.0f : __expf(s0.y - m0) * i0;
            float e20 = (s2.x == -CUDART_INF_F) ? 0.0f : __expf(s2.x - m0) * i0;
            float e21 = (s2.y == -CUDART_INF_F) ? 0.0f : __expf(s2.y - m0) * i0;
            float e10 = (s1.x == -CUDART_INF_F) ? 0.0f : __expf(s1.x - m1) * i1;
            float e11 = (s1.y == -CUDART_INF_F) ? 0.0f : __expf(s1.y - m1) * i1;
            float e30 = (s3.x == -CUDART_INF_F) ? 0.0f : __expf(s3.x - m1) * i1;
            float e31 = (s3.y == -CUDART_INF_F) ? 0.0f : __expf(s3.y - m1) * i1;
            // hi parts
            __nv_bfloat162 p;
            p.x = __float2bfloat16(e00); p.y = __float2bfloat16(e01);
            ah[mi][0] = *(uint32_t*)&p;
            al[mi][0] = pack2(e00 - __bfloat162float(p.x), e01 - __bfloat162float(p.y));
            p.x = __float2bfloat16(e10); p.y = __float2bfloat16(e11);
            ah[mi][1] = *(uint32_t*)&p;
            al[mi][1] = pack2(e10 - __bfloat162float(p.x), e11 - __bfloat162float(p.y));
            p.x = __float2bfloat16(e20); p.y = __float2bfloat16(e21);
            ah[mi][2] = *(uint32_t*)&p;
            al[mi][2] = pack2(e20 - __bfloat162float(p.x), e21 - __bfloat162float(p.y));
            p.x = __float2bfloat16(e30); p.y = __float2bfloat16(e31);
            ah[mi][3] = *(uint32_t*)&p;
            al[mi][3] = pack2(e30 - __bfloat162float(p.x), e31 - __bfloat162float(p.y));
        }
#pragma unroll
        for (int ni = 0; ni < 4; ni++) {
            size_t r0 = (size_t)(bh * 64 + wn + ni * 8 + g) * 512 + (k0 >> 1) + t;
            bh2[ni][0] = Vh[r0]; bh2[ni][1] = Vh[r0 + 4];
            bl2[ni][0] = Vl[r0]; bl2[ni][1] = Vl[r0 + 4];
        }
#pragma unroll
        for (int mi = 0; mi < 4; mi++)
#pragma unroll
            for (int ni = 0; ni < 4; ni++) {
                mma_bf16(acc[mi][ni], ah[mi], bh2[ni]);
                mma_bf16(acc[mi][ni], ah[mi], bl2[ni]);
                mma_bf16(acc[mi][ni], al[mi], bh2[ni]);
            }
    }

#pragma unroll
    for (int mi = 0; mi < 4; mi++)
#pragma unroll
        for (int ni = 0; ni < 4; ni++) {
            int row0 = b * 1024 + brow + wm + mi * 16 + g;
            int cn = h * 64 + wn + ni * 8 + 2 * t;
            *(float2*)&out[(size_t)row0 * 1024 + cn] =
                make_float2(acc[mi][ni][0], acc[mi][ni][1]);
            *(float2*)&out[(size_t)(row0 + 8) * 1024 + cn] =
                make_float2(acc[mi][ni][2], acc[mi][ni][3]);
        }
}

// ---------------------------------------------------------------------------
extern "C" void kernel_launch(void* const* d_in, const int* in_sizes, int n_in,
                              void* d_out, int out_size) {
    (void)in_sizes; (void)n_in; (void)out_size;
    const float* x    = (const float*)d_in[0];
    const float* Wqv  = (const float*)d_in[1];
    const float* rr   = (const float*)d_in[2];
    const float* rw   = (const float*)d_in[3];
    const int*   mask = (const int*)d_in[4];
    float* out = (float*)d_out;

    k_trig<<<1024, 32>>>();
    k_decomp_x<<<16384, 256>>>(x);
    k_decomp_w<<<8192, 256>>>(Wqv);
    k_qv_mma<<<dim3(16, 32), 256>>>(rr);
    k_vt<<<16384, 256>>>();
    k_build_A<<<256, 256>>>(rr, rw);
    k_build_K<<<256, 256>>>(x);
    k_sgemm<<<dim3(8, 8, 64), 256>>>(mask);
    k_combine<<<256, 256>>>();
    k_pv_mma<<<dim3(4, 64), 256>>>(out);
}

// round 7
// speedup vs baseline: 1.6159x; 1.5701x over previous
#include <cuda_runtime.h>
#include <cuda_bf16.h>
#include <math_constants.h>
#include <math.h>
#include <cstdint>

// B=4, L=1024, D=1024, H=16, HD=64.
// S[q,k] = (q+rr)·x_k + (q+rw)·pos[k-q+L] == Â[q]·K̂[k], K=128 (angle addition).

// ---------------------------------------------------------------------------
// Device scratch
// ---------------------------------------------------------------------------
__device__ __align__(16) __nv_bfloat16 g_xh[4096 * 1024];
__device__ __align__(16) __nv_bfloat16 g_xl[4096 * 1024];
__device__ __align__(16) __nv_bfloat16 g_wh[2048 * 1024];      // Wqv^T hi [n][k]
__device__ __align__(16) __nv_bfloat16 g_wl[2048 * 1024];
__device__ __align__(16) float g_u[4096 * 1024];               // q + rr
__device__ __align__(16) float g_v[4096 * 1024];               // v fp32
__device__ __align__(16) __nv_bfloat16 g_vth[64 * 64 * 1024];  // V^T hi [bh*64+d][tok]
__device__ __align__(16) __nv_bfloat16 g_vtl[64 * 64 * 1024];  // V^T lo
__device__ __align__(16) float g_trig[1024 * 64];              // [p][i]=sin, [p][32+i]=cos
__device__ __align__(16) __nv_bfloat16 g_Ah[(size_t)64 * 1024 * 128];
__device__ __align__(16) __nv_bfloat16 g_Al[(size_t)64 * 1024 * 128];
__device__ __align__(16) __nv_bfloat16 g_Kh[(size_t)64 * 1024 * 128];
__device__ __align__(16) __nv_bfloat16 g_Kl[(size_t)64 * 1024 * 128];
__device__ __align__(16) float g_S[(size_t)64 * 1024 * 1024];  // 256 MB
__device__ __align__(16) float g_pm[(size_t)65536 * 32];
__device__ __align__(16) float g_ps[(size_t)65536 * 32];
__device__ __align__(16) float g_m[65536];
__device__ __align__(16) float g_inv[65536];

// ---------------------------------------------------------------------------
// helpers
// ---------------------------------------------------------------------------
__device__ __forceinline__ uint32_t smem_u32(const void* p) {
    uint32_t a;
    asm("{ .reg .u64 t; cvta.to.shared.u64 t, %1; cvt.u32.u64 %0, t; }" : "=r"(a) : "l"(p));
    return a;
}
__device__ __forceinline__ void mma_bf16(float* c, const uint32_t* a, const uint32_t* b) {
    asm volatile(
        "mma.sync.aligned.m16n8k16.row.col.f32.bf16.bf16.f32 "
        "{%0,%1,%2,%3}, {%4,%5,%6,%7}, {%8,%9}, {%0,%1,%2,%3};"
        : "+f"(c[0]), "+f"(c[1]), "+f"(c[2]), "+f"(c[3])
        : "r"(a[0]), "r"(a[1]), "r"(a[2]), "r"(a[3]), "r"(b[0]), "r"(b[1]));
}
__device__ __forceinline__ void ldsm4(uint32_t* r, uint32_t addr) {
    asm volatile("ldmatrix.sync.aligned.m8n8.x4.shared.b16 {%0,%1,%2,%3}, [%4];"
        : "=r"(r[0]), "=r"(r[1]), "=r"(r[2]), "=r"(r[3]) : "r"(addr));
}
__device__ __forceinline__ uint32_t pack2(float e0, float e1) {
    __nv_bfloat162 h;
    h.x = __float2bfloat16(e0);
    h.y = __float2bfloat16(e1);
    return *(uint32_t*)&h;
}
#define CP16(saddr, gptr) \
    asm volatile("cp.async.ca.shared.global [%0], [%1], 16;" \
        :: "r"(saddr), "l"(__cvta_generic_to_global(gptr)))
#define CP_COMMIT() asm volatile("cp.async.commit_group;")
#define CP_WAIT(n)  asm volatile("cp.async.wait_group %0;" :: "n"(n))

// Stage layout (bytes within one 30720B stage):
//   A_h @0 (128 rows x 80B), A_l @10240, B_h @20480 (64 x 80B), B_l @25600
#define STAGE_BYTES 30720
#define SMEM_TOTAL  (2 * STAGE_BYTES)

// Load one 32-k-wide stage: A tile 128 rows, B tile 64 rows, both hi+lo.
__device__ __forceinline__ void stage_load(
    uint32_t sb, const __nv_bfloat16* Ah, const __nv_bfloat16* Al,
    const __nv_bfloat16* Bh, const __nv_bfloat16* Bl,
    size_t aRow, size_t bRow, int lda, int k0, int tid)
{
#pragma unroll
    for (int it = 0; it < 2; it++) {
        int idx = tid + it * 256;              // 0..511
        int r = idx >> 2, c = idx & 3;
        uint32_t so = r * 80 + c * 16;
        size_t go = (aRow + r) * (size_t)lda + k0 + c * 8;
        CP16(sb + so, Ah + go);
        CP16(sb + 10240 + so, Al + go);
    }
    {
        int r = tid >> 2, c = tid & 3;         // r 0..63
        uint32_t so = r * 80 + c * 16;
        size_t go = (bRow + r) * (size_t)lda + k0 + c * 8;
        CP16(sb + 20480 + so, Bh + go);
        CP16(sb + 25600 + so, Bl + go);
    }
}

// Compute one stage (two k-steps of 16) for a 32x32 warp tile.
__device__ __forceinline__ void stage_mma(uint32_t sb, int wm, int wn, int lane,
                                          float acc[2][4][4])
{
    int rsel = lane & 15;
    uint32_t csel = ((lane >> 4) << 3);
#pragma unroll
    for (int kc = 0; kc < 32; kc += 16) {
        uint32_t colB = (kc + csel) * 2;
        uint32_t ah[2][4], al[2][4], bhf[2][4], blf[2][4];
#pragma unroll
        for (int mi = 0; mi < 2; mi++) {
            uint32_t ad = sb + (uint32_t)((wm + mi * 16 + rsel) * 80) + colB;
            ldsm4(ah[mi], ad);
            ldsm4(al[mi], ad + 10240);
        }
#pragma unroll
        for (int p = 0; p < 2; p++) {
            uint32_t bd = sb + 20480 + (uint32_t)((wn + p * 16 + rsel) * 80) + colB;
            ldsm4(bhf[p], bd);
            ldsm4(blf[p], bd + 5120);
        }
#pragma unroll
        for (int mi = 0; mi < 2; mi++)
#pragma unroll
            for (int ni = 0; ni < 4; ni++) {
                int p = ni >> 1, o = ni & 1;
                uint32_t bq[2]  = { bhf[p][o], bhf[p][o + 2] };
                uint32_t bql[2] = { blf[p][o], blf[p][o + 2] };
                mma_bf16(acc[mi][ni], ah[mi], bq);
                mma_bf16(acc[mi][ni], ah[mi], bql);
                mma_bf16(acc[mi][ni], al[mi], bq);
            }
    }
}

// ---------------------------------------------------------------------------
// K0: trig table. K1: hi/lo decomposition of x and Wqv^T.
// ---------------------------------------------------------------------------
__global__ void k_trig() {
    int p = blockIdx.x, i = threadIdx.x;
    double f = exp(-(double)i * (log(10000.0) / 31.0));
    double ang = (double)p * f;
    g_trig[p * 64 + i] = (float)sin(ang);
    g_trig[p * 64 + 32 + i] = (float)cos(ang);
}
__global__ __launch_bounds__(256) void k_decomp_x(const float* __restrict__ x) {
    int idx = blockIdx.x * 256 + threadIdx.x;
    float f = x[idx];
    __nv_bfloat16 h = __float2bfloat16(f);
    g_xh[idx] = h;
    g_xl[idx] = __float2bfloat16(f - __bfloat162float(h));
}
__global__ __launch_bounds__(256) void k_decomp_w(const float* __restrict__ W) {
    int idx = blockIdx.x * 256 + threadIdx.x;
    int k = idx >> 11, n = idx & 2047;
    float f = W[idx];
    __nv_bfloat16 h = __float2bfloat16(f);
    g_wh[n * 1024 + k] = h;
    g_wl[n * 1024 + k] = __float2bfloat16(f - __bfloat162float(h));
}

// ---------------------------------------------------------------------------
// K2: qv = x @ Wqv. smem-staged cp.async + ldmatrix, 128x64 block, 8 warps.
// ---------------------------------------------------------------------------
__global__ __launch_bounds__(256, 2) void k_qv_mma(const float* __restrict__ rr) {
    extern __shared__ char dynsmem[];
    uint32_t sbase = smem_u32(dynsmem);
    int tid = threadIdx.x, wid = tid >> 5, lane = tid & 31;
    int wm = (wid >> 1) * 32, wn = (wid & 1) * 32;
    int g = lane >> 2, t = lane & 3;
    int brow = blockIdx.y * 128, bcol = blockIdx.x * 64;

    float acc[2][4][4] = {};
    const int NS = 32;                         // K=1024 / 32
    stage_load(sbase, g_xh, g_xl, g_wh, g_wl, brow, bcol, 1024, 0, tid);
    CP_COMMIT();
    for (int s = 0; s < NS; s++) {
        if (s + 1 < NS) {
            stage_load(sbase + ((s + 1) & 1) * STAGE_BYTES, g_xh, g_xl, g_wh, g_wl,
                       brow, bcol, 1024, (s + 1) * 32, tid);
            CP_COMMIT();
            CP_WAIT(1);
        } else {
            CP_WAIT(0);
        }
        __syncthreads();
        stage_mma(sbase + (s & 1) * STAGE_BYTES, wm, wn, lane, acc);
        __syncthreads();
    }

    bool is_q = (bcol < 1024);
#pragma unroll
    for (int mi = 0; mi < 2; mi++)
#pragma unroll
        for (int ni = 0; ni < 4; ni++) {
            int row0 = brow + wm + mi * 16 + g;
            int cn = bcol + wn + ni * 8 + 2 * t;
            float2 v0 = make_float2(acc[mi][ni][0], acc[mi][ni][1]);
            float2 v1 = make_float2(acc[mi][ni][2], acc[mi][ni][3]);
            if (is_q) {
                float2 rb = *(const float2*)(rr + cn);
                v0.x += rb.x; v0.y += rb.y;
                v1.x += rb.x; v1.y += rb.y;
                *(float2*)&g_u[(size_t)row0 * 1024 + cn] = v0;
                *(float2*)&g_u[(size_t)(row0 + 8) * 1024 + cn] = v1;
            } else {
                *(float2*)&g_v[(size_t)row0 * 1024 + cn - 1024] = v0;
                *(float2*)&g_v[(size_t)(row0 + 8) * 1024 + cn - 1024] = v1;
            }
        }
}

// ---------------------------------------------------------------------------
// K3: V^T bf16 hi/lo.
// ---------------------------------------------------------------------------
__global__ __launch_bounds__(256) void k_vt() {
    int idx = blockIdx.x * 256 + threadIdx.x;
    int tok = idx & 1023, d = (idx >> 10) & 63, bh = idx >> 16;
    int b = bh >> 4, h = bh & 15;
    float f = g_v[(size_t)(b * 1024 + tok) * 1024 + h * 64 + d];
    __nv_bfloat16 hi = __float2bfloat16(f);
    g_vth[idx] = hi;
    g_vtl[idx] = __float2bfloat16(f - __bfloat162float(hi));
}

// ---------------------------------------------------------------------------
// K4a/K4b: build Â and K̂ rows (hi/lo bf16, 128-wide).
// ---------------------------------------------------------------------------
__global__ __launch_bounds__(256) void k_build_A(const float* __restrict__ rr,
                                                 const float* __restrict__ rw) {
    int idx = blockIdx.x * 256 + threadIdx.x;
    int bh = idx >> 10, q = idx & 1023;
    int b = bh >> 4, h = bh & 15;
    const float* up = g_u + (size_t)(b * 1024 + q) * 1024 + h * 64;
    __nv_bfloat16* ah = g_Ah + (size_t)idx * 128;
    __nv_bfloat16* al = g_Al + (size_t)idx * 128;
    const float* tg = g_trig + q * 64;
#pragma unroll 8
    for (int i = 0; i < 32; i++) {
        float u0 = up[i], u1 = up[32 + i];
        __nv_bfloat16 h0 = __float2bfloat16(u0);
        ah[i] = h0; al[i] = __float2bfloat16(u0 - __bfloat162float(h0));
        __nv_bfloat16 h1 = __float2bfloat16(u1);
        ah[32 + i] = h1; al[32 + i] = __float2bfloat16(u1 - __bfloat162float(h1));
        float w0 = u0 - rr[h * 64 + i] + rw[h * 64 + i];
        float w1 = u1 - rr[h * 64 + 32 + i] + rw[h * 64 + 32 + i];
        float sq = tg[i], cq = tg[32 + i];
        float a1 = w0 * cq + w1 * sq;
        float a2 = w1 * cq - w0 * sq;
        __nv_bfloat16 hh1 = __float2bfloat16(a1);
        ah[64 + i] = hh1; al[64 + i] = __float2bfloat16(a1 - __bfloat162float(hh1));
        __nv_bfloat16 hh2 = __float2bfloat16(a2);
        ah[96 + i] = hh2; al[96 + i] = __float2bfloat16(a2 - __bfloat162float(hh2));
    }
}
__global__ __launch_bounds__(256) void k_build_K(const float* __restrict__ x) {
    int idx = blockIdx.x * 256 + threadIdx.x;
    int bh = idx >> 10, k = idx & 1023;
    int b = bh >> 4, h = bh & 15;
    const float* xp = x + (size_t)(b * 1024 + k) * 1024 + h * 64;
    __nv_bfloat16* kh = g_Kh + (size_t)idx * 128;
    __nv_bfloat16* kl = g_Kl + (size_t)idx * 128;
    const float* tg = g_trig + k * 64;
#pragma unroll 8
    for (int i = 0; i < 32; i++) {
        float x0 = xp[i], x1 = xp[32 + i];
        __nv_bfloat16 h0 = __float2bfloat16(x0);
        kh[i] = h0; kl[i] = __float2bfloat16(x0 - __bfloat162float(h0));
        __nv_bfloat16 h1 = __float2bfloat16(x1);
        kh[32 + i] = h1; kl[32 + i] = __float2bfloat16(x1 - __bfloat162float(h1));
        float s = tg[i], c = tg[32 + i];
        __nv_bfloat16 h2 = __float2bfloat16(s);
        kh[64 + i] = h2; kl[64 + i] = __float2bfloat16(s - __bfloat162float(h2));
        __nv_bfloat16 h3 = __float2bfloat16(c);
        kh[96 + i] = h3; kl[96 + i] = __float2bfloat16(c - __bfloat162float(h3));
    }
}

// ---------------------------------------------------------------------------
// K5: S = Â·K̂^T (K=128), smem-staged. Block 128q x 64k, 8 warps of 32x32.
// Epilogue: mask, store S, per-(row, 32k-slice) partial softmax stats.
// ---------------------------------------------------------------------------
__global__ __launch_bounds__(256, 2) void k_sgemm(const int* __restrict__ mask) {
    extern __shared__ char dynsmem[];
    __shared__ int msk[64];
    uint32_t sbase = smem_u32(dynsmem);
    int bh = blockIdx.z, b = bh >> 4;
    int brow = blockIdx.y * 128, bcol = blockIdx.x * 64;
    int tid = threadIdx.x, wid = tid >> 5, lane = tid & 31;
    int wm = (wid >> 1) * 32, wn = (wid & 1) * 32;
    int g = lane >> 2, t = lane & 3;
    if (tid < 64) msk[tid] = mask[b * 1024 + bcol + tid];

    size_t aRow = (size_t)bh * 1024 + brow;
    size_t kRow = (size_t)bh * 1024 + bcol;
    float acc[2][4][4] = {};
    const int NS = 4;                          // K=128 / 32
    stage_load(sbase, g_Ah, g_Al, g_Kh, g_Kl, aRow, kRow, 128, 0, tid);
    CP_COMMIT();
    for (int s = 0; s < NS; s++) {
        if (s + 1 < NS) {
            stage_load(sbase + ((s + 1) & 1) * STAGE_BYTES, g_Ah, g_Al, g_Kh, g_Kl,
                       aRow, kRow, 128, (s + 1) * 32, tid);
            CP_COMMIT();
            CP_WAIT(1);
        } else {
            CP_WAIT(0);
        }
        __syncthreads();
        stage_mma(sbase + (s & 1) * STAGE_BYTES, wm, wn, lane, acc);
        __syncthreads();
    }

    float* Sb = g_S + (size_t)bh * 1024 * 1024;
#pragma unroll
    for (int mi = 0; mi < 2; mi++)
#pragma unroll
        for (int half = 0; half < 2; half++) {
            int rloc = wm + mi * 16 + g + half * 8;
            float vmax = -CUDART_INF_F, vsum = 0.0f;
            float2 vs[4];
#pragma unroll
            for (int ni = 0; ni < 4; ni++) {
                int lk = wn + ni * 8 + 2 * t;
                float v0 = acc[mi][ni][half * 2 + 0];
                float v1 = acc[mi][ni][half * 2 + 1];
                if (msk[lk] == 0)     v0 = -CUDART_INF_F;
                if (msk[lk + 1] == 0) v1 = -CUDART_INF_F;
                vs[ni] = make_float2(v0, v1);
                vmax = fmaxf(vmax, fmaxf(v0, v1));
            }
            vmax = fmaxf(vmax, __shfl_xor_sync(0xffffffffu, vmax, 1));
            vmax = fmaxf(vmax, __shfl_xor_sync(0xffffffffu, vmax, 2));
#pragma unroll
            for (int ni = 0; ni < 4; ni++) {
                vsum += (vs[ni].x == -CUDART_INF_F) ? 0.0f : __expf(vs[ni].x - vmax);
                vsum += (vs[ni].y == -CUDART_INF_F) ? 0.0f : __expf(vs[ni].y - vmax);
                *(float2*)&Sb[(size_t)(brow + rloc) * 1024 + bcol + wn + ni * 8 + 2 * t] = vs[ni];
            }
            vsum += __shfl_xor_sync(0xffffffffu, vsum, 1);
            vsum += __shfl_xor_sync(0xffffffffu, vsum, 2);
            if (t == 0) {
                size_t sidx = ((size_t)bh * 1024 + brow + rloc) * 32
                            + blockIdx.x * 2 + (wid & 1);
                g_pm[sidx] = vmax;
                g_ps[sidx] = vsum;
            }
        }
}

// ---------------------------------------------------------------------------
// K6: combine 32 partials per row -> row max + 1/Z
// ---------------------------------------------------------------------------
__global__ __launch_bounds__(256) void k_combine() {
    int r = blockIdx.x * 256 + threadIdx.x;
    float m = -CUDART_INF_F;
#pragma unroll 8
    for (int t = 0; t < 32; t++) m = fmaxf(m, g_pm[(size_t)r * 32 + t]);
    float z = 0.0f;
#pragma unroll 8
    for (int t = 0; t < 32; t++) {
        float s = g_ps[(size_t)r * 32 + t];
        if (s > 0.0f) z += s * __expf(g_pm[(size_t)r * 32 + t] - m);
    }
    g_m[r] = m;
    g_inv[r] = 1.0f / z;
}

// ---------------------------------------------------------------------------
// K7: out = softmax(S) @ V via mma.sync. 256q x 64d block, 8 warps (4m x 2n).
// ---------------------------------------------------------------------------
__global__ __launch_bounds__(256) void k_pv_mma(float* __restrict__ out) {
    int bh = blockIdx.y, b = bh >> 4, h = bh & 15;
    int brow = blockIdx.x * 256;
    int tid = threadIdx.x, wid = tid >> 5, lane = tid & 31;
    int wm = (wid >> 1) * 64, wn = (wid & 1) * 32;
    int g = lane >> 2, t = lane & 3;

    const float* Sb = g_S + (size_t)bh * 1024 * 1024;
    const uint32_t* Vh = (const uint32_t*)g_vth;
    const uint32_t* Vl = (const uint32_t*)g_vtl;

    float mrow[4][2], irow[4][2];
#pragma unroll
    for (int mi = 0; mi < 4; mi++) {
        int r0 = bh * 1024 + brow + wm + mi * 16 + g;
        mrow[mi][0] = g_m[r0];     irow[mi][0] = g_inv[r0];
        mrow[mi][1] = g_m[r0 + 8]; irow[mi][1] = g_inv[r0 + 8];
    }

    float acc[4][4][4] = {};
    for (int k0 = 0; k0 < 1024; k0 += 16) {
        uint32_t ah[4][4], al[4][4], bh2[4][2], bl2[4][2];
#pragma unroll
        for (int mi = 0; mi < 4; mi++) {
            const float* r0 = Sb + (size_t)(brow + wm + mi * 16 + g) * 1024 + k0 + 2 * t;
            const float* r1 = r0 + 8 * 1024;
            float2 s0 = *(const float2*)(r0);
            float2 s2 = *(const float2*)(r0 + 8);
            float2 s1 = *(const float2*)(r1);
            float2 s3 = *(const float2*)(r1 + 8);
            float m0 = mrow[mi][0], i0 = irow[mi][0];
            float m1 = mrow[mi][1], i1 = irow[mi][1];
            float e00 = (s0.x == -CUDART_INF_F) ? 0.0f : __expf(s0.x - m0) * i0;
            float e01 = (s0.y == -CUDART_INF_F) ? 0.0f : __expf(s0.y - m0) * i0;
            float e20 = (s2.x == -CUDART_INF_F) ? 0.0f : __expf(s2.x - m0) * i0;
            float e21 = (s2.y == -CUDART_INF_F) ? 0.0f : __expf(s2.y - m0) * i0;
            float e10 = (s1.x == -CUDART_INF_F) ? 0.0f : __expf(s1.x - m1) * i1;
            float e11 = (s1.y == -CUDART_INF_F) ? 0.0f : __expf(s1.y - m1) * i1;
            float e30 = (s3.x == -CUDART_INF_F) ? 0.0f : __expf(s3.x - m1) * i1;
            float e31 = (s3.y == -CUDART_INF_F) ? 0.0f : __expf(s3.y - m1) * i1;
            __nv_bfloat162 p;
            p.x = __float2bfloat16(e00); p.y = __float2bfloat16(e01);
            ah[mi][0] = *(uint32_t*)&p;
            al[mi][0] = pack2(e00 - __bfloat162float(p.x), e01 - __bfloat162float(p.y));
            p.x = __float2bfloat16(e10); p.y = __float2bfloat16(e11);
            ah[mi][1] = *(uint32_t*)&p;
            al[mi][1] = pack2(e10 - __bfloat162float(p.x), e11 - __bfloat162float(p.y));
            p.x = __float2bfloat16(e20); p.y = __float2bfloat16(e21);
            ah[mi][2] = *(uint32_t*)&p;
            al[mi][2] = pack2(e20 - __bfloat162float(p.x), e21 - __bfloat162float(p.y));
            p.x = __float2bfloat16(e30); p.y = __float2bfloat16(e31);
            ah[mi][3] = *(uint32_t*)&p;
            al[mi][3] = pack2(e30 - __bfloat162float(p.x), e31 - __bfloat162float(p.y));
        }
#pragma unroll
        for (int ni = 0; ni < 4; ni++) {
            size_t r0 = (size_t)(bh * 64 + wn + ni * 8 + g) * 512 + (k0 >> 1) + t;
            bh2[ni][0] = Vh[r0]; bh2[ni][1] = Vh[r0 + 4];
            bl2[ni][0] = Vl[r0]; bl2[ni][1] = Vl[r0 + 4];
        }
#pragma unroll
        for (int mi = 0; mi < 4; mi++)
#pragma unroll
            for (int ni = 0; ni < 4; ni++) {
                mma_bf16(acc[mi][ni], ah[mi], bh2[ni]);
                mma_bf16(acc[mi][ni], ah[mi], bl2[ni]);
                mma_bf16(acc[mi][ni], al[mi], bh2[ni]);
            }
    }

#pragma unroll
    for (int mi = 0; mi < 4; mi++)
#pragma unroll
        for (int ni = 0; ni < 4; ni++) {
            int row0 = b * 1024 + brow + wm + mi * 16 + g;
            int cn = h * 64 + wn + ni * 8 + 2 * t;
            *(float2*)&out[(size_t)row0 * 1024 + cn] =
                make_float2(acc[mi][ni][0], acc[mi][ni][1]);
            *(float2*)&out[(size_t)(row0 + 8) * 1024 + cn] =
                make_float2(acc[mi][ni][2], acc[mi][ni][3]);
        }
}

// ---------------------------------------------------------------------------
extern "C" void kernel_launch(void* const* d_in, const int* in_sizes, int n_in,
                              void* d_out, int out_size) {
    (void)in_sizes; (void)n_in; (void)out_size;
    const float* x    = (const float*)d_in[0];
    const float* Wqv  = (const float*)d_in[1];
    const float* rr   = (const float*)d_in[2];
    const float* rw   = (const float*)d_in[3];
    const int*   mask = (const int*)d_in[4];
    float* out = (float*)d_out;

    cudaFuncSetAttribute(k_qv_mma, cudaFuncAttributeMaxDynamicSharedMemorySize, SMEM_TOTAL);
    cudaFuncSetAttribute(k_sgemm,  cudaFuncAttributeMaxDynamicSharedMemorySize, SMEM_TOTAL);

    k_trig<<<1024, 32>>>();
    k_decomp_x<<<16384, 256>>>(x);
    k_decomp_w<<<8192, 256>>>(Wqv);
    k_qv_mma<<<dim3(32, 32), 256, SMEM_TOTAL>>>(rr);
    k_vt<<<16384, 256>>>();
    k_build_A<<<256, 256>>>(rr, rw);
    k_build_K<<<256, 256>>>(x);
    k_sgemm<<<dim3(16, 8, 64), 256, SMEM_TOTAL>>>(mask);
    k_combine<<<256, 256>>>();
    k_pv_mma<<<dim3(4, 64), 256>>>(out);
}

// round 8
// speedup vs baseline: 1.7019x; 1.0532x over previous
#include <cuda_runtime.h>
#include <cuda_bf16.h>
#include <math_constants.h>
#include <math.h>
#include <cstdint>

// B=4, L=1024, D=1024, H=16, HD=64.
// S[q,k] = (q+rr)·x_k + (q+rw)·pos[k-q+L] == Â[q]·K̂[k], K=128 (angle addition).
// R8: flash-fused S·softmax·PV (no materialized S).

// ---------------------------------------------------------------------------
// Device scratch
// ---------------------------------------------------------------------------
__device__ __align__(16) __nv_bfloat16 g_xh[4096 * 1024];
__device__ __align__(16) __nv_bfloat16 g_xl[4096 * 1024];
__device__ __align__(16) __nv_bfloat16 g_wh[2048 * 1024];      // Wqv^T hi [n][k]
__device__ __align__(16) __nv_bfloat16 g_wl[2048 * 1024];
__device__ __align__(16) float g_u[4096 * 1024];               // q + rr
__device__ __align__(16) float g_v[4096 * 1024];               // v fp32
__device__ __align__(16) __nv_bfloat16 g_vth[64 * 64 * 1024];  // V^T hi [bh*64+d][tok]
__device__ __align__(16) __nv_bfloat16 g_vtl[64 * 64 * 1024];  // V^T lo
__device__ __align__(16) float g_trig[1024 * 64];              // [p][i]=sin, [p][32+i]=cos
__device__ __align__(16) __nv_bfloat16 g_Ah[(size_t)64 * 1024 * 128];
__device__ __align__(16) __nv_bfloat16 g_Al[(size_t)64 * 1024 * 128];
__device__ __align__(16) __nv_bfloat16 g_Kh[(size_t)64 * 1024 * 128];
__device__ __align__(16) __nv_bfloat16 g_Kl[(size_t)64 * 1024 * 128];

// ---------------------------------------------------------------------------
// helpers
// ---------------------------------------------------------------------------
__device__ __forceinline__ uint32_t smem_u32(const void* p) {
    uint32_t a;
    asm("{ .reg .u64 t; cvta.to.shared.u64 t, %1; cvt.u32.u64 %0, t; }" : "=r"(a) : "l"(p));
    return a;
}
__device__ __forceinline__ void mma_bf16(float* c, const uint32_t* a, const uint32_t* b) {
    asm volatile(
        "mma.sync.aligned.m16n8k16.row.col.f32.bf16.bf16.f32 "
        "{%0,%1,%2,%3}, {%4,%5,%6,%7}, {%8,%9}, {%0,%1,%2,%3};"
        : "+f"(c[0]), "+f"(c[1]), "+f"(c[2]), "+f"(c[3])
        : "r"(a[0]), "r"(a[1]), "r"(a[2]), "r"(a[3]), "r"(b[0]), "r"(b[1]));
}
__device__ __forceinline__ void ldsm4(uint32_t* r, uint32_t addr) {
    asm volatile("ldmatrix.sync.aligned.m8n8.x4.shared.b16 {%0,%1,%2,%3}, [%4];"
        : "=r"(r[0]), "=r"(r[1]), "=r"(r[2]), "=r"(r[3]) : "r"(addr));
}
__device__ __forceinline__ uint32_t pack2(float e0, float e1) {
    __nv_bfloat162 h;
    h.x = __float2bfloat16(e0);
    h.y = __float2bfloat16(e1);
    return *(uint32_t*)&h;
}
#define CP16(saddr, gptr) \
    asm volatile("cp.async.ca.shared.global [%0], [%1], 16;" \
        :: "r"(saddr), "l"(__cvta_generic_to_global(gptr)))
#define CP_COMMIT() asm volatile("cp.async.commit_group;")
#define CP_WAIT(n)  asm volatile("cp.async.wait_group %0;" :: "n"(n))

// ---------------------------------------------------------------------------
// K0: trig table. K1: hi/lo decomposition of x and Wqv^T.
// ---------------------------------------------------------------------------
__global__ void k_trig() {
    int p = blockIdx.x, i = threadIdx.x;
    double f = exp(-(double)i * (log(10000.0) / 31.0));
    double ang = (double)p * f;
    g_trig[p * 64 + i] = (float)sin(ang);
    g_trig[p * 64 + 32 + i] = (float)cos(ang);
}
__global__ __launch_bounds__(256) void k_decomp_x(const float* __restrict__ x) {
    int idx = blockIdx.x * 256 + threadIdx.x;
    float f = x[idx];
    __nv_bfloat16 h = __float2bfloat16(f);
    g_xh[idx] = h;
    g_xl[idx] = __float2bfloat16(f - __bfloat162float(h));
}
__global__ __launch_bounds__(256) void k_decomp_w(const float* __restrict__ W) {
    int idx = blockIdx.x * 256 + threadIdx.x;
    int k = idx >> 11, n = idx & 2047;
    float f = W[idx];
    __nv_bfloat16 h = __float2bfloat16(f);
    g_wh[n * 1024 + k] = h;
    g_wl[n * 1024 + k] = __float2bfloat16(f - __bfloat162float(h));
}

// ---------------------------------------------------------------------------
// K2: qv = x @ Wqv. smem-staged cp.async + ldmatrix (validated R7).
// ---------------------------------------------------------------------------
#define STAGE_BYTES 30720
#define QV_SMEM (2 * STAGE_BYTES)

__device__ __forceinline__ void stage_load(
    uint32_t sb, const __nv_bfloat16* Ah, const __nv_bfloat16* Al,
    const __nv_bfloat16* Bh, const __nv_bfloat16* Bl,
    size_t aRow, size_t bRow, int lda, int k0, int tid)
{
#pragma unroll
    for (int it = 0; it < 2; it++) {
        int idx = tid + it * 256;
        int r = idx >> 2, c = idx & 3;
        uint32_t so = r * 80 + c * 16;
        size_t go = (aRow + r) * (size_t)lda + k0 + c * 8;
        CP16(sb + so, Ah + go);
        CP16(sb + 10240 + so, Al + go);
    }
    {
        int r = tid >> 2, c = tid & 3;
        uint32_t so = r * 80 + c * 16;
        size_t go = (bRow + r) * (size_t)lda + k0 + c * 8;
        CP16(sb + 20480 + so, Bh + go);
        CP16(sb + 25600 + so, Bl + go);
    }
}
__device__ __forceinline__ void stage_mma(uint32_t sb, int wm, int wn, int lane,
                                          float acc[2][4][4])
{
    int rsel = lane & 15;
    uint32_t csel = ((lane >> 4) << 3);
#pragma unroll
    for (int kc = 0; kc < 32; kc += 16) {
        uint32_t colB = (kc + csel) * 2;
        uint32_t ah[2][4], al[2][4], bhf[2][4], blf[2][4];
#pragma unroll
        for (int mi = 0; mi < 2; mi++) {
            uint32_t ad = sb + (uint32_t)((wm + mi * 16 + rsel) * 80) + colB;
            ldsm4(ah[mi], ad);
            ldsm4(al[mi], ad + 10240);
        }
#pragma unroll
        for (int p = 0; p < 2; p++) {
            uint32_t bd = sb + 20480 + (uint32_t)((wn + p * 16 + rsel) * 80) + colB;
            ldsm4(bhf[p], bd);
            ldsm4(blf[p], bd + 5120);
        }
#pragma unroll
        for (int mi = 0; mi < 2; mi++)
#pragma unroll
            for (int ni = 0; ni < 4; ni++) {
                int p = ni >> 1, o = ni & 1;
                uint32_t bq[2]  = { bhf[p][o], bhf[p][o + 2] };
                uint32_t bql[2] = { blf[p][o], blf[p][o + 2] };
                mma_bf16(acc[mi][ni], ah[mi], bq);
                mma_bf16(acc[mi][ni], ah[mi], bql);
                mma_bf16(acc[mi][ni], al[mi], bq);
            }
    }
}

__global__ __launch_bounds__(256, 2) void k_qv_mma(const float* __restrict__ rr) {
    extern __shared__ char dynsmem[];
    uint32_t sbase = smem_u32(dynsmem);
    int tid = threadIdx.x, wid = tid >> 5, lane = tid & 31;
    int wm = (wid >> 1) * 32, wn = (wid & 1) * 32;
    int g = lane >> 2, t = lane & 3;
    int brow = blockIdx.y * 128, bcol = blockIdx.x * 64;

    float acc[2][4][4] = {};
    const int NS = 32;
    stage_load(sbase, g_xh, g_xl, g_wh, g_wl, brow, bcol, 1024, 0, tid);
    CP_COMMIT();
    for (int s = 0; s < NS; s++) {
        if (s + 1 < NS) {
            stage_load(sbase + ((s + 1) & 1) * STAGE_BYTES, g_xh, g_xl, g_wh, g_wl,
                       brow, bcol, 1024, (s + 1) * 32, tid);
            CP_COMMIT();
            CP_WAIT(1);
        } else {
            CP_WAIT(0);
        }
        __syncthreads();
        stage_mma(sbase + (s & 1) * STAGE_BYTES, wm, wn, lane, acc);
        __syncthreads();
    }

    bool is_q = (bcol < 1024);
#pragma unroll
    for (int mi = 0; mi < 2; mi++)
#pragma unroll
        for (int ni = 0; ni < 4; ni++) {
            int row0 = brow + wm + mi * 16 + g;
            int cn = bcol + wn + ni * 8 + 2 * t;
            float2 v0 = make_float2(acc[mi][ni][0], acc[mi][ni][1]);
            float2 v1 = make_float2(acc[mi][ni][2], acc[mi][ni][3]);
            if (is_q) {
                float2 rb = *(const float2*)(rr + cn);
                v0.x += rb.x; v0.y += rb.y;
                v1.x += rb.x; v1.y += rb.y;
                *(float2*)&g_u[(size_t)row0 * 1024 + cn] = v0;
                *(float2*)&g_u[(size_t)(row0 + 8) * 1024 + cn] = v1;
            } else {
                *(float2*)&g_v[(size_t)row0 * 1024 + cn - 1024] = v0;
                *(float2*)&g_v[(size_t)(row0 + 8) * 1024 + cn - 1024] = v1;
            }
        }
}

// ---------------------------------------------------------------------------
// K3: V^T bf16 hi/lo.
// ---------------------------------------------------------------------------
__global__ __launch_bounds__(256) void k_vt() {
    int idx = blockIdx.x * 256 + threadIdx.x;
    int tok = idx & 1023, d = (idx >> 10) & 63, bh = idx >> 16;
    int b = bh >> 4, h = bh & 15;
    float f = g_v[(size_t)(b * 1024 + tok) * 1024 + h * 64 + d];
    __nv_bfloat16 hi = __float2bfloat16(f);
    g_vth[idx] = hi;
    g_vtl[idx] = __float2bfloat16(f - __bfloat162float(hi));
}

// ---------------------------------------------------------------------------
// K4a/K4b: build Â and K̂ rows (hi/lo bf16, 128-wide).
// ---------------------------------------------------------------------------
__global__ __launch_bounds__(256) void k_build_A(const float* __restrict__ rr,
                                                 const float* __restrict__ rw) {
    int idx = blockIdx.x * 256 + threadIdx.x;
    int bh = idx >> 10, q = idx & 1023;
    int b = bh >> 4, h = bh & 15;
    const float* up = g_u + (size_t)(b * 1024 + q) * 1024 + h * 64;
    __nv_bfloat16* ah = g_Ah + (size_t)idx * 128;
    __nv_bfloat16* al = g_Al + (size_t)idx * 128;
    const float* tg = g_trig + q * 64;
#pragma unroll 8
    for (int i = 0; i < 32; i++) {
        float u0 = up[i], u1 = up[32 + i];
        __nv_bfloat16 h0 = __float2bfloat16(u0);
        ah[i] = h0; al[i] = __float2bfloat16(u0 - __bfloat162float(h0));
        __nv_bfloat16 h1 = __float2bfloat16(u1);
        ah[32 + i] = h1; al[32 + i] = __float2bfloat16(u1 - __bfloat162float(h1));
        float w0 = u0 - rr[h * 64 + i] + rw[h * 64 + i];
        float w1 = u1 - rr[h * 64 + 32 + i] + rw[h * 64 + 32 + i];
        float sq = tg[i], cq = tg[32 + i];
        float a1 = w0 * cq + w1 * sq;
        float a2 = w1 * cq - w0 * sq;
        __nv_bfloat16 hh1 = __float2bfloat16(a1);
        ah[64 + i] = hh1; al[64 + i] = __float2bfloat16(a1 - __bfloat162float(hh1));
        __nv_bfloat16 hh2 = __float2bfloat16(a2);
        ah[96 + i] = hh2; al[96 + i] = __float2bfloat16(a2 - __bfloat162float(hh2));
    }
}
__global__ __launch_bounds__(256) void k_build_K(const float* __restrict__ x) {
    int idx = blockIdx.x * 256 + threadIdx.x;
    int bh = idx >> 10, k = idx & 1023;
    int b = bh >> 4, h = bh & 15;
    const float* xp = x + (size_t)(b * 1024 + k) * 1024 + h * 64;
    __nv_bfloat16* kh = g_Kh + (size_t)idx * 128;
    __nv_bfloat16* kl = g_Kl + (size_t)idx * 128;
    const float* tg = g_trig + k * 64;
#pragma unroll 8
    for (int i = 0; i < 32; i++) {
        float x0 = xp[i], x1 = xp[32 + i];
        __nv_bfloat16 h0 = __float2bfloat16(x0);
        kh[i] = h0; kl[i] = __float2bfloat16(x0 - __bfloat162float(h0));
        __nv_bfloat16 h1 = __float2bfloat16(x1);
        kh[32 + i] = h1; kl[32 + i] = __float2bfloat16(x1 - __bfloat162float(h1));
        float s = tg[i], c = tg[32 + i];
        __nv_bfloat16 h2 = __float2bfloat16(s);
        kh[64 + i] = h2; kl[64 + i] = __float2bfloat16(s - __bfloat162float(h2));
        __nv_bfloat16 h3 = __float2bfloat16(c);
        kh[96 + i] = h3; kl[96 + i] = __float2bfloat16(c - __bfloat162float(h3));
    }
}

// ---------------------------------------------------------------------------
// K5: flash attention. Block = 128 q rows x (all 1024 k), 8 warps of 16q.
// Â (128x128 hi/lo) smem-resident; K̂ double-buffered (64-k tiles); online
// softmax in registers; PV accumulated via 3-split MMA with V^T from global.
//
// smem layout (80B rows, 32-col chunks — validated ldmatrix addressing):
//   Â  hi: chunk c at c*10240 (128 rows x 80B);  lo at +40960.  [0, 81920)
//   K̂  stage s at 81920 + s*40960:
//      hi: chunk c at +c*5120 (64 rows x 80B);   lo at +20480.
// ---------------------------------------------------------------------------
#define FA_ACH 10240
#define FA_ALO 40960
#define FA_KBASE 81920
#define FA_KCH 5120
#define FA_KLO 20480
#define FA_KSTAGE 40960
#define FA_SMEM (FA_KBASE + 2 * FA_KSTAGE)   // 163840

__global__ __launch_bounds__(256, 1) void k_flash(const int* __restrict__ mask,
                                                  float* __restrict__ out) {
    extern __shared__ char dynsmem[];
    __shared__ int msk[1024];
    uint32_t sb = smem_u32(dynsmem);
    int bh = blockIdx.y, b = bh >> 4, h = bh & 15;
    int brow = blockIdx.x * 128;
    int tid = threadIdx.x, wid = tid >> 5, lane = tid & 31;
    int wm = wid * 16;
    int g = lane >> 2, t = lane & 3;
    int rsel = lane & 15;
    uint32_t csel = ((lane >> 4) << 3);

    size_t aRow = (size_t)bh * 1024 + brow;
    size_t kRow = (size_t)bh * 1024;

    // ---- load Â (once) ----
#pragma unroll
    for (int it = 0; it < 8; it++) {
        int idx = tid + it * 256;              // 0..2047
        int r = idx >> 4, cc = idx & 15;
        uint32_t so = (cc >> 2) * FA_ACH + r * 80 + (cc & 3) * 16;
        size_t go = (aRow + r) * 128 + cc * 8;
        CP16(sb + so, g_Ah + go);
        CP16(sb + FA_ALO + so, g_Al + go);
    }
    // ---- load K̂ stage 0 ----
#pragma unroll
    for (int it = 0; it < 4; it++) {
        int idx = tid + it * 256;              // 0..1023
        int r = idx >> 4, cc = idx & 15;
        uint32_t so = FA_KBASE + (cc >> 2) * FA_KCH + r * 80 + (cc & 3) * 16;
        size_t go = (kRow + r) * 128 + cc * 8;
        CP16(sb + so, g_Kh + go);
        CP16(sb + FA_KLO + so, g_Kl + go);
    }
    CP_COMMIT();
    for (int i = tid; i < 1024; i += 256) msk[i] = mask[b * 1024 + i];

    const uint32_t* Vh = (const uint32_t*)g_vth;
    const uint32_t* Vl = (const uint32_t*)g_vtl;

    float oacc[8][4] = {};
    float m0 = -CUDART_INF_F, m1 = -CUDART_INF_F, l0 = 0.0f, l1 = 0.0f;

    const int NT = 16;
    for (int kt = 0; kt < NT; kt++) {
        if (kt + 1 < NT) {
            uint32_t st = sb + FA_KBASE + ((kt + 1) & 1) * FA_KSTAGE;
#pragma unroll
            for (int it = 0; it < 4; it++) {
                int idx = tid + it * 256;
                int r = idx >> 4, cc = idx & 15;
                uint32_t so = (cc >> 2) * FA_KCH + r * 80 + (cc & 3) * 16;
                size_t go = (kRow + (kt + 1) * 64 + r) * 128 + cc * 8;
                CP16(st + so, g_Kh + go);
                CP16(st + FA_KLO + so, g_Kl + go);
            }
            CP_COMMIT();
            CP_WAIT(1);
        } else {
            CP_WAIT(0);
        }
        __syncthreads();

        // ---- S tile: 16q x 64k per warp, K=128 ----
        uint32_t Ks = sb + FA_KBASE + (kt & 1) * FA_KSTAGE;
        float sacc[8][4] = {};
#pragma unroll
        for (int ks = 0; ks < 8; ks++) {
            int c = ks >> 1;
            uint32_t colB = (((ks & 1) * 16) + csel) * 2;
            uint32_t ah[4], al[4], bhf[4][4], blf[4][4];
            uint32_t ad = sb + (uint32_t)(c * FA_ACH) + (uint32_t)((wm + rsel) * 80) + colB;
            ldsm4(ah, ad);
            ldsm4(al, ad + FA_ALO);
#pragma unroll
            for (int p = 0; p < 4; p++) {
                uint32_t kd = Ks + (uint32_t)(c * FA_KCH) + (uint32_t)((p * 16 + rsel) * 80) + colB;
                ldsm4(bhf[p], kd);
                ldsm4(blf[p], kd + FA_KLO);
            }
#pragma unroll
            for (int ni = 0; ni < 8; ni++) {
                int p = ni >> 1, o = ni & 1;
                uint32_t bq[2]  = { bhf[p][o], bhf[p][o + 2] };
                uint32_t bql[2] = { blf[p][o], blf[p][o + 2] };
                mma_bf16(sacc[ni], ah, bq);
                mma_bf16(sacc[ni], ah, bql);
                mma_bf16(sacc[ni], al, bq);
            }
        }
        __syncthreads();   // release K̂ stage (kt&1) for the kt+1-issued load of kt+2

        // ---- online softmax ----
        int kb = kt * 64;
        float tmax0 = -CUDART_INF_F, tmax1 = -CUDART_INF_F;
#pragma unroll
        for (int ni = 0; ni < 8; ni++) {
            int kc = kb + ni * 8 + 2 * t;
            if (msk[kc] == 0)     { sacc[ni][0] = -CUDART_INF_F; sacc[ni][2] = -CUDART_INF_F; }
            if (msk[kc + 1] == 0) { sacc[ni][1] = -CUDART_INF_F; sacc[ni][3] = -CUDART_INF_F; }
            tmax0 = fmaxf(tmax0, fmaxf(sacc[ni][0], sacc[ni][1]));
            tmax1 = fmaxf(tmax1, fmaxf(sacc[ni][2], sacc[ni][3]));
        }
        tmax0 = fmaxf(tmax0, __shfl_xor_sync(0xffffffffu, tmax0, 1));
        tmax0 = fmaxf(tmax0, __shfl_xor_sync(0xffffffffu, tmax0, 2));
        tmax1 = fmaxf(tmax1, __shfl_xor_sync(0xffffffffu, tmax1, 1));
        tmax1 = fmaxf(tmax1, __shfl_xor_sync(0xffffffffu, tmax1, 2));
        float nm0 = fmaxf(m0, tmax0), nm1 = fmaxf(m1, tmax1);
        float sc0 = __expf(m0 - nm0), sc1 = __expf(m1 - nm1);
        m0 = nm0; m1 = nm1;

        float rs0 = 0.0f, rs1 = 0.0f;
        uint32_t aPh[4][4], aPl[4][4];
#pragma unroll
        for (int ni = 0; ni < 8; ni++) {
            float p0 = __expf(sacc[ni][0] - nm0);
            float p1 = __expf(sacc[ni][1] - nm0);
            float p2 = __expf(sacc[ni][2] - nm1);
            float p3 = __expf(sacc[ni][3] - nm1);
            rs0 += p0 + p1;
            rs1 += p2 + p3;
            int c2 = ni >> 1, o = ni & 1;
            __nv_bfloat162 hp;
            hp.x = __float2bfloat16(p0); hp.y = __float2bfloat16(p1);
            aPh[c2][o * 2 + 0] = *(uint32_t*)&hp;
            aPl[c2][o * 2 + 0] = pack2(p0 - __bfloat162float(hp.x), p1 - __bfloat162float(hp.y));
            hp.x = __float2bfloat16(p2); hp.y = __float2bfloat16(p3);
            aPh[c2][o * 2 + 1] = *(uint32_t*)&hp;
            aPl[c2][o * 2 + 1] = pack2(p2 - __bfloat162float(hp.x), p3 - __bfloat162float(hp.y));
        }
        rs0 += __shfl_xor_sync(0xffffffffu, rs0, 1);
        rs0 += __shfl_xor_sync(0xffffffffu, rs0, 2);
        rs1 += __shfl_xor_sync(0xffffffffu, rs1, 1);
        rs1 += __shfl_xor_sync(0xffffffffu, rs1, 2);
        l0 = l0 * sc0 + rs0;
        l1 = l1 * sc1 + rs1;
#pragma unroll
        for (int ni2 = 0; ni2 < 8; ni2++) {
            oacc[ni2][0] *= sc0; oacc[ni2][1] *= sc0;
            oacc[ni2][2] *= sc1; oacc[ni2][3] *= sc1;
        }

        // ---- PV: O += P @ V (V^T from global, validated addressing) ----
#pragma unroll
        for (int c2 = 0; c2 < 4; c2++) {
            int k0 = kb + c2 * 16;
#pragma unroll
            for (int ni2 = 0; ni2 < 8; ni2++) {
                size_t r0 = (size_t)(bh * 64 + ni2 * 8 + g) * 512 + (k0 >> 1) + t;
                uint32_t bvh[2] = { Vh[r0], Vh[r0 + 4] };
                uint32_t bvl[2] = { Vl[r0], Vl[r0 + 4] };
                mma_bf16(oacc[ni2], aPh[c2], bvh);
                mma_bf16(oacc[ni2], aPh[c2], bvl);
                mma_bf16(oacc[ni2], aPl[c2], bvh);
            }
        }
    }

    // ---- epilogue ----
    float inv0 = 1.0f / l0, inv1 = 1.0f / l1;
    int row0 = b * 1024 + brow + wm + g;
    int row1 = row0 + 8;
#pragma unroll
    for (int ni2 = 0; ni2 < 8; ni2++) {
        int cn = h * 64 + ni2 * 8 + 2 * t;
        *(float2*)&out[(size_t)row0 * 1024 + cn] =
            make_float2(oacc[ni2][0] * inv0, oacc[ni2][1] * inv0);
        *(float2*)&out[(size_t)row1 * 1024 + cn] =
            make_float2(oacc[ni2][2] * inv1, oacc[ni2][3] * inv1);
    }
}

// ---------------------------------------------------------------------------
extern "C" void kernel_launch(void* const* d_in, const int* in_sizes, int n_in,
                              void* d_out, int out_size) {
    (void)in_sizes; (void)n_in; (void)out_size;
    const float* x    = (const float*)d_in[0];
    const float* Wqv  = (const float*)d_in[1];
    const float* rr   = (const float*)d_in[2];
    const float* rw   = (const float*)d_in[3];
    const int*   mask = (const int*)d_in[4];
    float* out = (float*)d_out;

    cudaFuncSetAttribute(k_qv_mma, cudaFuncAttributeMaxDynamicSharedMemorySize, QV_SMEM);
    cudaFuncSetAttribute(k_flash,  cudaFuncAttributeMaxDynamicSharedMemorySize, FA_SMEM);

    k_trig<<<1024, 32>>>();
    k_decomp_x<<<16384, 256>>>(x);
    k_decomp_w<<<8192, 256>>>(Wqv);
    k_qv_mma<<<dim3(32, 32), 256, QV_SMEM>>>(rr);
    k_vt<<<16384, 256>>>();
    k_build_A<<<256, 256>>>(rr, rw);
    k_build_K<<<256, 256>>>(x);
    k_flash<<<dim3(8, 64), 256, FA_SMEM>>>(mask, out);
}

// round 9
// speedup vs baseline: 2.2661x; 1.3316x over previous
#include <cuda_runtime.h>
#include <cuda_bf16.h>
#include <math_constants.h>
#include <math.h>
#include <cstdint>

// B=4, L=1024, D=1024, H=16, HD=64.
// S[q,k] = (q+rr)·x_k + (q+rw)·pos[k-q+L] == Â[q]·K̂[k], K=128 (angle addition).
// R9: flash tail with V^T staged in smem (cp.async double-buffer + ldmatrix).

// ---------------------------------------------------------------------------
// Device scratch
// ---------------------------------------------------------------------------
__device__ __align__(16) __nv_bfloat16 g_xh[4096 * 1024];
__device__ __align__(16) __nv_bfloat16 g_xl[4096 * 1024];
__device__ __align__(16) __nv_bfloat16 g_wh[2048 * 1024];      // Wqv^T hi [n][k]
__device__ __align__(16) __nv_bfloat16 g_wl[2048 * 1024];
__device__ __align__(16) float g_u[4096 * 1024];               // q + rr
__device__ __align__(16) float g_v[4096 * 1024];               // v fp32
__device__ __align__(16) __nv_bfloat16 g_vth[64 * 64 * 1024];  // V^T hi [bh*64+d][tok]
__device__ __align__(16) __nv_bfloat16 g_vtl[64 * 64 * 1024];  // V^T lo
__device__ __align__(16) float g_trig[1024 * 64];              // [p][i]=sin, [p][32+i]=cos
__device__ __align__(16) __nv_bfloat16 g_Ah[(size_t)64 * 1024 * 128];
__device__ __align__(16) __nv_bfloat16 g_Al[(size_t)64 * 1024 * 128];
__device__ __align__(16) __nv_bfloat16 g_Kh[(size_t)64 * 1024 * 128];
__device__ __align__(16) __nv_bfloat16 g_Kl[(size_t)64 * 1024 * 128];

// ---------------------------------------------------------------------------
// helpers
// ---------------------------------------------------------------------------
__device__ __forceinline__ uint32_t smem_u32(const void* p) {
    uint32_t a;
    asm("{ .reg .u64 t; cvta.to.shared.u64 t, %1; cvt.u32.u64 %0, t; }" : "=r"(a) : "l"(p));
    return a;
}
__device__ __forceinline__ void mma_bf16(float* c, const uint32_t* a, const uint32_t* b) {
    asm volatile(
        "mma.sync.aligned.m16n8k16.row.col.f32.bf16.bf16.f32 "
        "{%0,%1,%2,%3}, {%4,%5,%6,%7}, {%8,%9}, {%0,%1,%2,%3};"
        : "+f"(c[0]), "+f"(c[1]), "+f"(c[2]), "+f"(c[3])
        : "r"(a[0]), "r"(a[1]), "r"(a[2]), "r"(a[3]), "r"(b[0]), "r"(b[1]));
}
__device__ __forceinline__ void ldsm4(uint32_t* r, uint32_t addr) {
    asm volatile("ldmatrix.sync.aligned.m8n8.x4.shared.b16 {%0,%1,%2,%3}, [%4];"
        : "=r"(r[0]), "=r"(r[1]), "=r"(r[2]), "=r"(r[3]) : "r"(addr));
}
__device__ __forceinline__ uint32_t pack2(float e0, float e1) {
    __nv_bfloat162 h;
    h.x = __float2bfloat16(e0);
    h.y = __float2bfloat16(e1);
    return *(uint32_t*)&h;
}
#define CP16(saddr, gptr) \
    asm volatile("cp.async.ca.shared.global [%0], [%1], 16;" \
        :: "r"(saddr), "l"(__cvta_generic_to_global(gptr)))
#define CP_COMMIT() asm volatile("cp.async.commit_group;")
#define CP_WAIT(n)  asm volatile("cp.async.wait_group %0;" :: "n"(n))

// ---------------------------------------------------------------------------
// K0: trig table. K1: hi/lo decomposition of x and Wqv^T.
// ---------------------------------------------------------------------------
__global__ void k_trig() {
    int p = blockIdx.x, i = threadIdx.x;
    double f = exp(-(double)i * (log(10000.0) / 31.0));
    double ang = (double)p * f;
    g_trig[p * 64 + i] = (float)sin(ang);
    g_trig[p * 64 + 32 + i] = (float)cos(ang);
}
__global__ __launch_bounds__(256) void k_decomp_x(const float* __restrict__ x) {
    int idx = blockIdx.x * 256 + threadIdx.x;
    float f = x[idx];
    __nv_bfloat16 h = __float2bfloat16(f);
    g_xh[idx] = h;
    g_xl[idx] = __float2bfloat16(f - __bfloat162float(h));
}
__global__ __launch_bounds__(256) void k_decomp_w(const float* __restrict__ W) {
    int idx = blockIdx.x * 256 + threadIdx.x;
    int k = idx >> 11, n = idx & 2047;
    float f = W[idx];
    __nv_bfloat16 h = __float2bfloat16(f);
    g_wh[n * 1024 + k] = h;
    g_wl[n * 1024 + k] = __float2bfloat16(f - __bfloat162float(h));
}

// ---------------------------------------------------------------------------
// K2: qv = x @ Wqv. smem-staged cp.async + ldmatrix (validated R7).
// ---------------------------------------------------------------------------
#define STAGE_BYTES 30720
#define QV_SMEM (2 * STAGE_BYTES)

__device__ __forceinline__ void stage_load(
    uint32_t sb, const __nv_bfloat16* Ah, const __nv_bfloat16* Al,
    const __nv_bfloat16* Bh, const __nv_bfloat16* Bl,
    size_t aRow, size_t bRow, int lda, int k0, int tid)
{
#pragma unroll
    for (int it = 0; it < 2; it++) {
        int idx = tid + it * 256;
        int r = idx >> 2, c = idx & 3;
        uint32_t so = r * 80 + c * 16;
        size_t go = (aRow + r) * (size_t)lda + k0 + c * 8;
        CP16(sb + so, Ah + go);
        CP16(sb + 10240 + so, Al + go);
    }
    {
        int r = tid >> 2, c = tid & 3;
        uint32_t so = r * 80 + c * 16;
        size_t go = (bRow + r) * (size_t)lda + k0 + c * 8;
        CP16(sb + 20480 + so, Bh + go);
        CP16(sb + 25600 + so, Bl + go);
    }
}
__device__ __forceinline__ void stage_mma(uint32_t sb, int wm, int wn, int lane,
                                          float acc[2][4][4])
{
    int rsel = lane & 15;
    uint32_t csel = ((lane >> 4) << 3);
#pragma unroll
    for (int kc = 0; kc < 32; kc += 16) {
        uint32_t colB = (kc + csel) * 2;
        uint32_t ah[2][4], al[2][4], bhf[2][4], blf[2][4];
#pragma unroll
        for (int mi = 0; mi < 2; mi++) {
            uint32_t ad = sb + (uint32_t)((wm + mi * 16 + rsel) * 80) + colB;
            ldsm4(ah[mi], ad);
            ldsm4(al[mi], ad + 10240);
        }
#pragma unroll
        for (int p = 0; p < 2; p++) {
            uint32_t bd = sb + 20480 + (uint32_t)((wn + p * 16 + rsel) * 80) + colB;
            ldsm4(bhf[p], bd);
            ldsm4(blf[p], bd + 5120);
        }
#pragma unroll
        for (int mi = 0; mi < 2; mi++)
#pragma unroll
            for (int ni = 0; ni < 4; ni++) {
                int p = ni >> 1, o = ni & 1;
                uint32_t bq[2]  = { bhf[p][o], bhf[p][o + 2] };
                uint32_t bql[2] = { blf[p][o], blf[p][o + 2] };
                mma_bf16(acc[mi][ni], ah[mi], bq);
                mma_bf16(acc[mi][ni], ah[mi], bql);
                mma_bf16(acc[mi][ni], al[mi], bq);
            }
    }
}

__global__ __launch_bounds__(256, 2) void k_qv_mma(const float* __restrict__ rr) {
    extern __shared__ char dynsmem[];
    uint32_t sbase = smem_u32(dynsmem);
    int tid = threadIdx.x, wid = tid >> 5, lane = tid & 31;
    int wm = (wid >> 1) * 32, wn = (wid & 1) * 32;
    int g = lane >> 2, t = lane & 3;
    int brow = blockIdx.y * 128, bcol = blockIdx.x * 64;

    float acc[2][4][4] = {};
    const int NS = 32;
    stage_load(sbase, g_xh, g_xl, g_wh, g_wl, brow, bcol, 1024, 0, tid);
    CP_COMMIT();
    for (int s = 0; s < NS; s++) {
        if (s + 1 < NS) {
            stage_load(sbase + ((s + 1) & 1) * STAGE_BYTES, g_xh, g_xl, g_wh, g_wl,
                       brow, bcol, 1024, (s + 1) * 32, tid);
            CP_COMMIT();
            CP_WAIT(1);
        } else {
            CP_WAIT(0);
        }
        __syncthreads();
        stage_mma(sbase + (s & 1) * STAGE_BYTES, wm, wn, lane, acc);
        __syncthreads();
    }

    bool is_q = (bcol < 1024);
#pragma unroll
    for (int mi = 0; mi < 2; mi++)
#pragma unroll
        for (int ni = 0; ni < 4; ni++) {
            int row0 = brow + wm + mi * 16 + g;
            int cn = bcol + wn + ni * 8 + 2 * t;
            float2 v0 = make_float2(acc[mi][ni][0], acc[mi][ni][1]);
            float2 v1 = make_float2(acc[mi][ni][2], acc[mi][ni][3]);
            if (is_q) {
                float2 rb = *(const float2*)(rr + cn);
                v0.x += rb.x; v0.y += rb.y;
                v1.x += rb.x; v1.y += rb.y;
                *(float2*)&g_u[(size_t)row0 * 1024 + cn] = v0;
                *(float2*)&g_u[(size_t)(row0 + 8) * 1024 + cn] = v1;
            } else {
                *(float2*)&g_v[(size_t)row0 * 1024 + cn - 1024] = v0;
                *(float2*)&g_v[(size_t)(row0 + 8) * 1024 + cn - 1024] = v1;
            }
        }
}

// ---------------------------------------------------------------------------
// K3: V^T bf16 hi/lo.
// ---------------------------------------------------------------------------
__global__ __launch_bounds__(256) void k_vt() {
    int idx = blockIdx.x * 256 + threadIdx.x;
    int tok = idx & 1023, d = (idx >> 10) & 63, bh = idx >> 16;
    int b = bh >> 4, h = bh & 15;
    float f = g_v[(size_t)(b * 1024 + tok) * 1024 + h * 64 + d];
    __nv_bfloat16 hi = __float2bfloat16(f);
    g_vth[idx] = hi;
    g_vtl[idx] = __float2bfloat16(f - __bfloat162float(hi));
}

// ---------------------------------------------------------------------------
// K4a/K4b: build Â and K̂ rows (hi/lo bf16, 128-wide).
// ---------------------------------------------------------------------------
__global__ __launch_bounds__(256) void k_build_A(const float* __restrict__ rr,
                                                 const float* __restrict__ rw) {
    int idx = blockIdx.x * 256 + threadIdx.x;
    int bh = idx >> 10, q = idx & 1023;
    int b = bh >> 4, h = bh & 15;
    const float* up = g_u + (size_t)(b * 1024 + q) * 1024 + h * 64;
    __nv_bfloat16* ah = g_Ah + (size_t)idx * 128;
    __nv_bfloat16* al = g_Al + (size_t)idx * 128;
    const float* tg = g_trig + q * 64;
#pragma unroll 8
    for (int i = 0; i < 32; i++) {
        float u0 = up[i], u1 = up[32 + i];
        __nv_bfloat16 h0 = __float2bfloat16(u0);
        ah[i] = h0; al[i] = __float2bfloat16(u0 - __bfloat162float(h0));
        __nv_bfloat16 h1 = __float2bfloat16(u1);
        ah[32 + i] = h1; al[32 + i] = __float2bfloat16(u1 - __bfloat162float(h1));
        float w0 = u0 - rr[h * 64 + i] + rw[h * 64 + i];
        float w1 = u1 - rr[h * 64 + 32 + i] + rw[h * 64 + 32 + i];
        float sq = tg[i], cq = tg[32 + i];
        float a1 = w0 * cq + w1 * sq;
        float a2 = w1 * cq - w0 * sq;
        __nv_bfloat16 hh1 = __float2bfloat16(a1);
        ah[64 + i] = hh1; al[64 + i] = __float2bfloat16(a1 - __bfloat162float(hh1));
        __nv_bfloat16 hh2 = __float2bfloat16(a2);
        ah[96 + i] = hh2; al[96 + i] = __float2bfloat16(a2 - __bfloat162float(hh2));
    }
}
__global__ __launch_bounds__(256) void k_build_K(const float* __restrict__ x) {
    int idx = blockIdx.x * 256 + threadIdx.x;
    int bh = idx >> 10, k = idx & 1023;
    int b = bh >> 4, h = bh & 15;
    const float* xp = x + (size_t)(b * 1024 + k) * 1024 + h * 64;
    __nv_bfloat16* kh = g_Kh + (size_t)idx * 128;
    __nv_bfloat16* kl = g_Kl + (size_t)idx * 128;
    const float* tg = g_trig + k * 64;
#pragma unroll 8
    for (int i = 0; i < 32; i++) {
        float x0 = xp[i], x1 = xp[32 + i];
        __nv_bfloat16 h0 = __float2bfloat16(x0);
        kh[i] = h0; kl[i] = __float2bfloat16(x0 - __bfloat162float(h0));
        __nv_bfloat16 h1 = __float2bfloat16(x1);
        kh[32 + i] = h1; kl[32 + i] = __float2bfloat16(x1 - __bfloat162float(h1));
        float s = tg[i], c = tg[32 + i];
        __nv_bfloat16 h2 = __float2bfloat16(s);
        kh[64 + i] = h2; kl[64 + i] = __float2bfloat16(s - __bfloat162float(h2));
        __nv_bfloat16 h3 = __float2bfloat16(c);
        kh[96 + i] = h3; kl[96 + i] = __float2bfloat16(c - __bfloat162float(h3));
    }
}

// ---------------------------------------------------------------------------
// K5: flash attention. Block = 128 q rows x all k, 8 warps of 16q.
// Â smem-resident; K̂ AND V^T double-buffered via cp.async; online softmax;
// PV via ldmatrix from the V smem stage (no more scalar V LDGs).
//
// smem (80B rows, 32-col chunks — validated layout):
//   Â  hi chunk c @ c*10240 (128 rows); lo at +40960.      [0, 81920)
//   K̂  stage s @ 81920 + s*40960: hi chunk c @ +c*5120 (64 rows); lo +20480.
//   V  stage s @ 163840 + s*20480: hi chunk c @ +c*5120 (64 d-rows x 32 tok); lo +10240.
// ---------------------------------------------------------------------------
#define FA_ACH 10240
#define FA_ALO 40960
#define FA_KBASE 81920
#define FA_KCH 5120
#define FA_KLO 20480
#define FA_KSTAGE 40960
#define FA_VBASE 163840
#define FA_VCH 5120
#define FA_VLO 10240
#define FA_VSTAGE 20480
#define FA_SMEM (FA_VBASE + 2 * FA_VSTAGE)   // 204800

__device__ __forceinline__ void fa_load_kv(uint32_t sb, int bh, size_t kRow,
                                           int kb, int buf, int tid) {
    uint32_t stK = sb + FA_KBASE + buf * FA_KSTAGE;
    uint32_t stV = sb + FA_VBASE + buf * FA_VSTAGE;
#pragma unroll
    for (int it = 0; it < 4; it++) {
        int idx = tid + it * 256;              // 0..1023
        int r = idx >> 4, cc = idx & 15;
        uint32_t so = (cc >> 2) * FA_KCH + r * 80 + (cc & 3) * 16;
        size_t go = (kRow + kb + r) * 128 + cc * 8;
        CP16(stK + so, g_Kh + go);
        CP16(stK + FA_KLO + so, g_Kl + go);
    }
#pragma unroll
    for (int it = 0; it < 2; it++) {
        int idx = tid + it * 256;              // 0..511
        int r = idx >> 3, cc = idx & 7;        // r: d-row 0..63
        int c = cc >> 2, c4 = cc & 3;
        uint32_t so = c * FA_VCH + r * 80 + c4 * 16;
        size_t go = (size_t)(bh * 64 + r) * 1024 + kb + c * 32 + c4 * 8;
        CP16(stV + so, g_vth + go);
        CP16(stV + FA_VLO + so, g_vtl + go);
    }
}

__global__ __launch_bounds__(256, 1) void k_flash(const int* __restrict__ mask,
                                                  float* __restrict__ out) {
    extern __shared__ char dynsmem[];
    __shared__ int msk[1024];
    uint32_t sb = smem_u32(dynsmem);
    int bh = blockIdx.y, b = bh >> 4, h = bh & 15;
    int brow = blockIdx.x * 128;
    int tid = threadIdx.x, wid = tid >> 5, lane = tid & 31;
    int wm = wid * 16;
    int g = lane >> 2, t = lane & 3;
    int rsel = lane & 15;
    uint32_t csel = ((lane >> 4) << 3);

    size_t aRow = (size_t)bh * 1024 + brow;
    size_t kRow = (size_t)bh * 1024;

    // ---- load Â (once) ----
#pragma unroll
    for (int it = 0; it < 8; it++) {
        int idx = tid + it * 256;
        int r = idx >> 4, cc = idx & 15;
        uint32_t so = (cc >> 2) * FA_ACH + r * 80 + (cc & 3) * 16;
        size_t go = (aRow + r) * 128 + cc * 8;
        CP16(sb + so, g_Ah + go);
        CP16(sb + FA_ALO + so, g_Al + go);
    }
    // ---- load K̂+V stage 0 ----
    fa_load_kv(sb, bh, kRow, 0, 0, tid);
    CP_COMMIT();
    for (int i = tid; i < 1024; i += 256) msk[i] = mask[b * 1024 + i];

    float oacc[8][4] = {};
    float m0 = -CUDART_INF_F, m1 = -CUDART_INF_F, l0 = 0.0f, l1 = 0.0f;

    const int NT = 16;
    for (int kt = 0; kt < NT; kt++) {
        if (kt + 1 < NT) {
            fa_load_kv(sb, bh, kRow, (kt + 1) * 64, (kt + 1) & 1, tid);
            CP_COMMIT();
            CP_WAIT(1);
        } else {
            CP_WAIT(0);
        }
        __syncthreads();

        // ---- S tile: 16q x 64k per warp, K=128 ----
        uint32_t Ks = sb + FA_KBASE + (kt & 1) * FA_KSTAGE;
        float sacc[8][4] = {};
#pragma unroll
        for (int ks = 0; ks < 8; ks++) {
            int c = ks >> 1;
            uint32_t colB = (((ks & 1) * 16) + csel) * 2;
            uint32_t ah[4], al[4], bhf[4][4], blf[4][4];
            uint32_t ad = sb + (uint32_t)(c * FA_ACH) + (uint32_t)((wm + rsel) * 80) + colB;
            ldsm4(ah, ad);
            ldsm4(al, ad + FA_ALO);
#pragma unroll
            for (int p = 0; p < 4; p++) {
                uint32_t kd = Ks + (uint32_t)(c * FA_KCH) + (uint32_t)((p * 16 + rsel) * 80) + colB;
                ldsm4(bhf[p], kd);
                ldsm4(blf[p], kd + FA_KLO);
            }
#pragma unroll
            for (int ni = 0; ni < 8; ni++) {
                int p = ni >> 1, o = ni & 1;
                uint32_t bq[2]  = { bhf[p][o], bhf[p][o + 2] };
                uint32_t bql[2] = { blf[p][o], blf[p][o + 2] };
                mma_bf16(sacc[ni], ah, bq);
                mma_bf16(sacc[ni], ah, bql);
                mma_bf16(sacc[ni], al, bq);
            }
        }

        // ---- online softmax ----
        int kb = kt * 64;
        float tmax0 = -CUDART_INF_F, tmax1 = -CUDART_INF_F;
#pragma unroll
        for (int ni = 0; ni < 8; ni++) {
            int kc = kb + ni * 8 + 2 * t;
            if (msk[kc] == 0)     { sacc[ni][0] = -CUDART_INF_F; sacc[ni][2] = -CUDART_INF_F; }
            if (msk[kc + 1] == 0) { sacc[ni][1] = -CUDART_INF_F; sacc[ni][3] = -CUDART_INF_F; }
            tmax0 = fmaxf(tmax0, fmaxf(sacc[ni][0], sacc[ni][1]));
            tmax1 = fmaxf(tmax1, fmaxf(sacc[ni][2], sacc[ni][3]));
        }
        tmax0 = fmaxf(tmax0, __shfl_xor_sync(0xffffffffu, tmax0, 1));
        tmax0 = fmaxf(tmax0, __shfl_xor_sync(0xffffffffu, tmax0, 2));
        tmax1 = fmaxf(tmax1, __shfl_xor_sync(0xffffffffu, tmax1, 1));
        tmax1 = fmaxf(tmax1, __shfl_xor_sync(0xffffffffu, tmax1, 2));
        float nm0 = fmaxf(m0, tmax0), nm1 = fmaxf(m1, tmax1);
        float sc0 = __expf(m0 - nm0), sc1 = __expf(m1 - nm1);
        m0 = nm0; m1 = nm1;

        float rs0 = 0.0f, rs1 = 0.0f;
        uint32_t aPh[4][4], aPl[4][4];
#pragma unroll
        for (int ni = 0; ni < 8; ni++) {
            float p0 = __expf(sacc[ni][0] - nm0);
            float p1 = __expf(sacc[ni][1] - nm0);
            float p2 = __expf(sacc[ni][2] - nm1);
            float p3 = __expf(sacc[ni][3] - nm1);
            rs0 += p0 + p1;
            rs1 += p2 + p3;
            int c2 = ni >> 1, o = ni & 1;
            __nv_bfloat162 hp;
            hp.x = __float2bfloat16(p0); hp.y = __float2bfloat16(p1);
            aPh[c2][o * 2 + 0] = *(uint32_t*)&hp;
            aPl[c2][o * 2 + 0] = pack2(p0 - __bfloat162float(hp.x), p1 - __bfloat162float(hp.y));
            hp.x = __float2bfloat16(p2); hp.y = __float2bfloat16(p3);
            aPh[c2][o * 2 + 1] = *(uint32_t*)&hp;
            aPl[c2][o * 2 + 1] = pack2(p2 - __bfloat162float(hp.x), p3 - __bfloat162float(hp.y));
        }
        rs0 += __shfl_xor_sync(0xffffffffu, rs0, 1);
        rs0 += __shfl_xor_sync(0xffffffffu, rs0, 2);
        rs1 += __shfl_xor_sync(0xffffffffu, rs1, 1);
        rs1 += __shfl_xor_sync(0xffffffffu, rs1, 2);
        l0 = l0 * sc0 + rs0;
        l1 = l1 * sc1 + rs1;
#pragma unroll
        for (int ni2 = 0; ni2 < 8; ni2++) {
            oacc[ni2][0] *= sc0; oacc[ni2][1] *= sc0;
            oacc[ni2][2] *= sc1; oacc[ni2][3] *= sc1;
        }

        // ---- PV: O += P @ V from smem V stage (ldmatrix) ----
        uint32_t Vs = sb + FA_VBASE + (kt & 1) * FA_VSTAGE;
#pragma unroll
        for (int c2 = 0; c2 < 4; c2++) {
            int c = c2 >> 1;
            uint32_t colB = (((c2 & 1) * 16) + csel) * 2;
            uint32_t bvh[4][4], bvl[4][4];
#pragma unroll
            for (int p = 0; p < 4; p++) {
                uint32_t vd = Vs + (uint32_t)(c * FA_VCH) + (uint32_t)((p * 16 + rsel) * 80) + colB;
                ldsm4(bvh[p], vd);
                ldsm4(bvl[p], vd + FA_VLO);
            }
#pragma unroll
            for (int ni2 = 0; ni2 < 8; ni2++) {
                int p = ni2 >> 1, o = ni2 & 1;
                uint32_t bq[2]  = { bvh[p][o], bvh[p][o + 2] };
                uint32_t bql[2] = { bvl[p][o], bvl[p][o + 2] };
                mma_bf16(oacc[ni2], aPh[c2], bq);
                mma_bf16(oacc[ni2], aPh[c2], bql);
                mma_bf16(oacc[ni2], aPl[c2], bq);
            }
        }
        __syncthreads();   // release stage (kt&1) before it is refilled in iter kt+1
    }

    // ---- epilogue ----
    float inv0 = 1.0f / l0, inv1 = 1.0f / l1;
    int row0 = b * 1024 + brow + wm + g;
    int row1 = row0 + 8;
#pragma unroll
    for (int ni2 = 0; ni2 < 8; ni2++) {
        int cn = h * 64 + ni2 * 8 + 2 * t;
        *(float2*)&out[(size_t)row0 * 1024 + cn] =
            make_float2(oacc[ni2][0] * inv0, oacc[ni2][1] * inv0);
        *(float2*)&out[(size_t)row1 * 1024 + cn] =
            make_float2(oacc[ni2][2] * inv1, oacc[ni2][3] * inv1);
    }
}

// ---------------------------------------------------------------------------
extern "C" void kernel_launch(void* const* d_in, const int* in_sizes, int n_in,
                              void* d_out, int out_size) {
    (void)in_sizes; (void)n_in; (void)out_size;
    const float* x    = (const float*)d_in[0];
    const float* Wqv  = (const float*)d_in[1];
    const float* rr   = (const float*)d_in[2];
    const float* rw   = (const float*)d_in[3];
    const int*   mask = (const int*)d_in[4];
    float* out = (float*)d_out;

    cudaFuncSetAttribute(k_qv_mma, cudaFuncAttributeMaxDynamicSharedMemorySize, QV_SMEM);
    cudaFuncSetAttribute(k_flash,  cudaFuncAttributeMaxDynamicSharedMemorySize, FA_SMEM);

    k_trig<<<1024, 32>>>();
    k_decomp_x<<<16384, 256>>>(x);
    k_decomp_w<<<8192, 256>>>(Wqv);
    k_qv_mma<<<dim3(32, 32), 256, QV_SMEM>>>(rr);
    k_vt<<<16384, 256>>>();
    k_build_A<<<256, 256>>>(rr, rw);
    k_build_K<<<256, 256>>>(x);
    k_flash<<<dim3(8, 64), 256, FA_SMEM>>>(mask, out);
}